// round 1
// baseline (speedup 1.0000x reference)
#include <cuda_runtime.h>
#include <math.h>
#include <float.h>

#define NN 100000
#define EE 400000
#define GG 32
#define HH 6
#define HD 192

// ---------------- scratch (device globals; no allocations allowed) ----------
__device__ float g_h[NN * HD];
__device__ float g_q[NN * HD];
__device__ float g_k[NN * HD];
__device__ float g_v[NN * HD];
__device__ float g_s[NN * HD];
__device__ float g_agg[NN * HD];
__device__ float g_m[NN * HH];
__device__ float g_z[NN * HH];
__device__ float g_p[EE * HH];
__device__ float g_pool[GG * HD];
__device__ float g_cnt[GG];

// ---------------- helpers ---------------------------------------------------
__device__ __forceinline__ void atomicMaxF(float* addr, float v) {
    if (v >= 0.0f)
        atomicMax((int*)addr, __float_as_int(v));
    else
        atomicMin((unsigned int*)addr, __float_as_uint(v));
}

__device__ __forceinline__ void redAddV4(float* addr, float4 v) {
    asm volatile("red.global.add.v4.f32 [%0], {%1,%2,%3,%4};"
                 :: "l"(addr), "f"(v.x), "f"(v.y), "f"(v.z), "f"(v.w)
                 : "memory");
}

// block reduce over 192 threads (6 warps)
__device__ __forceinline__ float blk_sum(float v, float* red) {
    int t = threadIdx.x, lane = t & 31, w = t >> 5;
#pragma unroll
    for (int o = 16; o; o >>= 1) v += __shfl_xor_sync(0xffffffffu, v, o);
    __syncthreads();
    if (lane == 0) red[w] = v;
    __syncthreads();
    float s = 0.f;
#pragma unroll
    for (int i = 0; i < 6; i++) s += red[i];
    return s;
}

// ---------------- input projection: h = x @ Wp + bp -------------------------
__global__ void proj_kernel(const float* __restrict__ x,
                            const float* __restrict__ Wp,
                            const float* __restrict__ bp) {
    int i = blockIdx.x * blockDim.x + threadIdx.x;
    if (i >= NN * HD) return;
    int n = i / HD, d = i - n * HD;
    const float* xr = x + n * 4;
    float acc = bp[d];
    acc += xr[0] * Wp[d] + xr[1] * Wp[HD + d] + xr[2] * Wp[2 * HD + d] + xr[3] * Wp[3 * HD + d];
    g_h[i] = acc;
}

// ---------------- fused q,k,v,skip GEMM: [N,192]@[192,192]+bias -------------
// grid = (N/32, 4), block = 256. BM=32, BN=192 (full), BK=16. Thread tile 2x12.
__global__ __launch_bounds__(256) void gemm4_kernel(
    const float* __restrict__ W0, const float* __restrict__ W1,
    const float* __restrict__ W2, const float* __restrict__ W3,
    const float* __restrict__ B0, const float* __restrict__ B1,
    const float* __restrict__ B2, const float* __restrict__ B3) {
    const float* W; const float* Bv; float* O;
    switch (blockIdx.y) {
        case 0:  W = W0; Bv = B0; O = g_q; break;
        case 1:  W = W1; Bv = B1; O = g_k; break;
        case 2:  W = W2; Bv = B2; O = g_v; break;
        default: W = W3; Bv = B3; O = g_s; break;
    }
    __shared__ float sA[HD * 33];                 // A^T tile: sA[k*33+m]
    __shared__ __align__(16) float sB[16 * HD];   // W chunk
    int tid = threadIdx.x;
    int row0 = blockIdx.x * 32;
    for (int i = tid; i < 32 * HD; i += 256) {
        int m = i / HD, k = i - m * HD;
        sA[k * 33 + m] = g_h[(row0 + m) * HD + k];
    }
    float acc[2][12];
#pragma unroll
    for (int r = 0; r < 2; r++)
#pragma unroll
        for (int j = 0; j < 12; j++) acc[r][j] = 0.f;
    int tx = tid & 15, ty = tid >> 4;
    int m0 = ty * 2, c0 = tx * 12;

    for (int kk = 0; kk < HD; kk += 16) {
        __syncthreads();
        for (int i = tid; i < 16 * HD; i += 256) {
            int k = i / HD, c = i - k * HD;
            sB[i] = W[(kk + k) * HD + c];
        }
        __syncthreads();
#pragma unroll
        for (int k = 0; k < 16; k++) {
            float a0 = sA[(kk + k) * 33 + m0];
            float a1 = sA[(kk + k) * 33 + m0 + 1];
            const float* br = &sB[k * HD + c0];
            float4 b0 = *reinterpret_cast<const float4*>(br);
            float4 b1 = *reinterpret_cast<const float4*>(br + 4);
            float4 b2 = *reinterpret_cast<const float4*>(br + 8);
            float bb[12] = {b0.x, b0.y, b0.z, b0.w, b1.x, b1.y, b1.z, b1.w,
                            b2.x, b2.y, b2.z, b2.w};
#pragma unroll
            for (int j = 0; j < 12; j++) {
                acc[0][j] += a0 * bb[j];
                acc[1][j] += a1 * bb[j];
            }
        }
    }
#pragma unroll
    for (int r = 0; r < 2; r++) {
        int row = row0 + m0 + r;
#pragma unroll
        for (int jv = 0; jv < 3; jv++) {
            float4 o;
            o.x = acc[r][jv * 4 + 0] + Bv[c0 + jv * 4 + 0];
            o.y = acc[r][jv * 4 + 1] + Bv[c0 + jv * 4 + 1];
            o.z = acc[r][jv * 4 + 2] + Bv[c0 + jv * 4 + 2];
            o.w = acc[r][jv * 4 + 3] + Bv[c0 + jv * 4 + 3];
            *reinterpret_cast<float4*>(&O[row * HD + c0 + jv * 4]) = o;
        }
    }
}

// ---------------- per-layer init: agg=0, z=0, m=-inf ------------------------
__global__ void init_layer_kernel() {
    int i = blockIdx.x * blockDim.x + threadIdx.x;
    if (i < NN * HD) g_agg[i] = 0.f;
    if (i < NN * HH) { g_z[i] = 0.f; g_m[i] = -FLT_MAX; }
}

// ---------------- edge logits + segment max (warp per edge) -----------------
__global__ void edge_logits_kernel(const int* __restrict__ src,
                                   const int* __restrict__ dst,
                                   const float* __restrict__ ew,
                                   const float* __restrict__ We) {
    int e = blockIdx.x * 8 + (threadIdx.x >> 5);
    int lane = threadIdx.x & 31;
    if (e >= EE) return;
    int s = src[e], d = dst[e];
    float w = ew[e];
    float acc[HH];
#pragma unroll
    for (int j = 0; j < HH; j++) {
        int dim = lane + 32 * j;
        float ke = g_k[s * HD + dim] + w * We[dim];
        acc[j] = g_q[d * HD + dim] * ke;
    }
#pragma unroll
    for (int o = 16; o; o >>= 1) {
#pragma unroll
        for (int j = 0; j < HH; j++) acc[j] += __shfl_xor_sync(0xffffffffu, acc[j], o);
    }
    const float scale = 0.17677669529663687f;  // 1/sqrt(32)
#pragma unroll
    for (int j = 0; j < HH; j++) {
        if (lane == j) {
            float lg = acc[j] * scale;
            g_p[e * HH + j] = lg;
            atomicMaxF(&g_m[d * HH + j], lg);
        }
    }
}

// ---------------- p = exp(logit - m[dst]); z += p ---------------------------
__global__ void softmax_pz_kernel(const int* __restrict__ dst) {
    int i = blockIdx.x * blockDim.x + threadIdx.x;
    if (i >= EE * HH) return;
    int e = i / HH, hh = i - e * HH;
    int d = dst[e];
    float p = expf(g_p[i] - g_m[d * HH + hh]);
    g_p[i] = p;
    atomicAdd(&g_z[d * HH + hh], p);
}

// ---------------- message aggregation (warp per edge, float4 REDs) ----------
__global__ void edge_agg_kernel(const int* __restrict__ src,
                                const int* __restrict__ dst,
                                const float* __restrict__ ew,
                                const float* __restrict__ We) {
    int e = blockIdx.x * 8 + (threadIdx.x >> 5);
    int lane = threadIdx.x & 31;
    if (e >= EE) return;
    int s = src[e], d = dst[e];
    float w = ew[e];
    float pv = 0.f;
    if (lane < HH) pv = g_p[e * HH + lane] / g_z[d * HH + lane];
    float a0 = __shfl_sync(0xffffffffu, pv, lane >> 3);
    float a1 = __shfl_sync(0xffffffffu, pv, 4 + (lane >> 3));

    int d0 = 4 * lane;  // dims 0..127, head = lane/8
    float4 v4 = *reinterpret_cast<const float4*>(&g_v[s * HD + d0]);
    float4 w4 = *reinterpret_cast<const float4*>(&We[d0]);
    float4 msg;
    msg.x = (v4.x + w * w4.x) * a0;
    msg.y = (v4.y + w * w4.y) * a0;
    msg.z = (v4.z + w * w4.z) * a0;
    msg.w = (v4.w + w * w4.w) * a0;
    redAddV4(&g_agg[d * HD + d0], msg);

    if (lane < 16) {  // dims 128..191, head = 4 + lane/8
        int d1 = 128 + 4 * lane;
        float4 v5 = *reinterpret_cast<const float4*>(&g_v[s * HD + d1]);
        float4 w5 = *reinterpret_cast<const float4*>(&We[d1]);
        float4 m2;
        m2.x = (v5.x + w * w5.x) * a1;
        m2.y = (v5.y + w * w5.y) * a1;
        m2.z = (v5.z + w * w5.z) * a1;
        m2.w = (v5.w + w * w5.w) * a1;
        redAddV4(&g_agg[d * HD + d1], m2);
    }
}

// ---------------- hi = agg + skip; h += relu(LN(hi)) (warp per node) --------
__global__ void ln_res_kernel(const float* __restrict__ lg,
                              const float* __restrict__ lb) {
    int n = blockIdx.x * 8 + (threadIdx.x >> 5);
    int lane = threadIdx.x & 31;
    if (n >= NN) return;
    float v[HH];
    float s1 = 0.f;
#pragma unroll
    for (int j = 0; j < HH; j++) {
        int dim = lane + 32 * j;
        v[j] = g_agg[n * HD + dim] + g_s[n * HD + dim];
        s1 += v[j];
    }
#pragma unroll
    for (int o = 16; o; o >>= 1) s1 += __shfl_xor_sync(0xffffffffu, s1, o);
    float mu = s1 * (1.0f / HD);
    float s2 = 0.f;
#pragma unroll
    for (int j = 0; j < HH; j++) { float dd = v[j] - mu; s2 += dd * dd; }
#pragma unroll
    for (int o = 16; o; o >>= 1) s2 += __shfl_xor_sync(0xffffffffu, s2, o);
    float rstd = rsqrtf(s2 * (1.0f / HD) + 1e-5f);
#pragma unroll
    for (int j = 0; j < HH; j++) {
        int dim = lane + 32 * j;
        float y = (v[j] - mu) * rstd * lg[dim] + lb[dim];
        g_h[n * HD + dim] += fmaxf(y, 0.f);
    }
}

// ---------------- pooling ----------------------------------------------------
__global__ void pool_init_kernel() {
    int i = blockIdx.x * blockDim.x + threadIdx.x;
    if (i < GG * HD) g_pool[i] = 0.f;
    if (i < GG) g_cnt[i] = 0.f;
}

__global__ void pool_kernel(const int* __restrict__ batch) {
    __shared__ float acc[GG * HD];
    __shared__ float scnt[GG];
    int t = threadIdx.x;  // 192
    for (int i = t; i < GG * HD; i += HD) acc[i] = 0.f;
    if (t < GG) scnt[t] = 0.f;
    __syncthreads();
    int per = (NN + gridDim.x - 1) / gridDim.x;
    int n0 = blockIdx.x * per;
    int n1 = min(n0 + per, NN);
    for (int n = n0; n < n1; n++) {
        int g = batch[n];
        acc[g * HD + t] += g_h[n * HD + t];
        if (t == 0) scnt[g] += 1.f;
    }
    __syncthreads();
    for (int i = t; i < GG * HD; i += HD) atomicAdd(&g_pool[i], acc[i]);
    if (t < GG) atomicAdd(&g_cnt[t], scnt[t]);
}

// ---------------- head MLP (block per graph, 192 threads) -------------------
__global__ void head_kernel(const float* __restrict__ ie,
                            const float* __restrict__ fciW, const float* __restrict__ fcib,
                            const float* __restrict__ fcig, const float* __restrict__ fcilb,
                            const float* __restrict__ fc1W, const float* __restrict__ fc1b,
                            const float* __restrict__ fc1g, const float* __restrict__ fc1lb,
                            const float* __restrict__ fc2W, const float* __restrict__ fc2b,
                            const float* __restrict__ fc2g, const float* __restrict__ fc2lb,
                            const float* __restrict__ fc3W, const float* __restrict__ fc3b,
                            float* __restrict__ out) {
    __shared__ float zin[2 * HD];
    __shared__ float buf[HD];
    __shared__ float red[8];
    int t = threadIdx.x;  // 0..191
    int g = blockIdx.x;

    float cnt = fmaxf(g_cnt[g], 1.f);
    zin[t] = g_pool[g * HD + t] / cnt;

    // fc_initial: Linear(1,192) + LN + ReLU
    float iv = ie[g] * fciW[t] + fcib[t];
    float mu = blk_sum(iv, red) * (1.0f / HD);
    float dv = iv - mu;
    float var = blk_sum(dv * dv, red) * (1.0f / HD);
    float rstd = rsqrtf(var + 1e-5f);
    zin[HD + t] = fmaxf(dv * rstd * fcig[t] + fcilb[t], 0.f);
    __syncthreads();

    // fc1: 384 -> 192, LN, ReLU
    float a = fc1b[t];
    for (int k = 0; k < 2 * HD; k++) a += zin[k] * fc1W[k * HD + t];
    mu = blk_sum(a, red) * (1.0f / HD);
    dv = a - mu;
    var = blk_sum(dv * dv, red) * (1.0f / HD);
    rstd = rsqrtf(var + 1e-5f);
    buf[t] = fmaxf(dv * rstd * fc1g[t] + fc1lb[t], 0.f);
    __syncthreads();

    // fc2: 192 -> 96, LN, ReLU
    float a2 = 0.f;
    if (t < 96) {
        a2 = fc2b[t];
        for (int k = 0; k < HD; k++) a2 += buf[k] * fc2W[k * 96 + t];
    }
    mu = blk_sum(t < 96 ? a2 : 0.f, red) * (1.0f / 96.0f);
    dv = a2 - mu;
    var = blk_sum(t < 96 ? dv * dv : 0.f, red) * (1.0f / 96.0f);
    rstd = rsqrtf(var + 1e-5f);
    float r2 = 0.f;
    if (t < 96) r2 = fmaxf(dv * rstd * fc2g[t] + fc2lb[t], 0.f);

    // fc3: 96 -> 1
    float p3 = (t < 96) ? r2 * fc3W[t] : 0.f;
    float tot = blk_sum(p3, red);
    if (t == 0) out[g] = tot + fc3b[0];
}

// ---------------- launch ------------------------------------------------------
extern "C" void kernel_launch(void* const* d_in, const int* in_sizes, int n_in,
                              void* d_out, int out_size) {
    const float* x    = (const float*)d_in[0];
    const int*   ei   = (const int*)d_in[1];
    const float* ew   = (const float*)d_in[2];
    const int*   batch= (const int*)d_in[3];
    const float* ie   = (const float*)d_in[4];
    const float* Wp   = (const float*)d_in[5];
    const float* bp   = (const float*)d_in[6];
    const float* Wq   = (const float*)d_in[7];
    const float* bq   = (const float*)d_in[8];
    const float* Wk   = (const float*)d_in[9];
    const float* bk   = (const float*)d_in[10];
    const float* Wv   = (const float*)d_in[11];
    const float* bv   = (const float*)d_in[12];
    const float* We   = (const float*)d_in[13];
    const float* Ws   = (const float*)d_in[14];
    const float* bs   = (const float*)d_in[15];
    const float* lng  = (const float*)d_in[16];
    const float* lnb  = (const float*)d_in[17];
    const float* fciW = (const float*)d_in[18];
    const float* fcib = (const float*)d_in[19];
    const float* fcig = (const float*)d_in[20];
    const float* fcilb= (const float*)d_in[21];
    const float* fc1W = (const float*)d_in[22];
    const float* fc1b = (const float*)d_in[23];
    const float* fc1g = (const float*)d_in[24];
    const float* fc1lb= (const float*)d_in[25];
    const float* fc2W = (const float*)d_in[26];
    const float* fc2b = (const float*)d_in[27];
    const float* fc2g = (const float*)d_in[28];
    const float* fc2lb= (const float*)d_in[29];
    const float* fc3W = (const float*)d_in[30];
    const float* fc3b = (const float*)d_in[31];
    float* out = (float*)d_out;

    const int* src = ei;
    const int* dst = ei + EE;

    proj_kernel<<<(NN * HD + 255) / 256, 256>>>(x, Wp, bp);

    for (int i = 0; i < 3; i++) {
        gemm4_kernel<<<dim3(NN / 32, 4), 256>>>(
            Wq + i * HD * HD, Wk + i * HD * HD, Wv + i * HD * HD, Ws + i * HD * HD,
            bq + i * HD, bk + i * HD, bv + i * HD, bs + i * HD);
        init_layer_kernel<<<(NN * HD + 255) / 256, 256>>>();
        edge_logits_kernel<<<EE / 8, 256>>>(src, dst, ew, We + i * HD);
        softmax_pz_kernel<<<(EE * HH + 255) / 256, 256>>>(dst);
        edge_agg_kernel<<<EE / 8, 256>>>(src, dst, ew, We + i * HD);
        ln_res_kernel<<<NN / 8, 256>>>(lng + i * HD, lnb + i * HD);
    }

    pool_init_kernel<<<(GG * HD + 255) / 256, 256>>>();
    pool_kernel<<<512, HD>>>(batch);
    head_kernel<<<GG, HD>>>(ie, fciW, fcib, fcig, fcilb,
                            fc1W, fc1b, fc1g, fc1lb,
                            fc2W, fc2b, fc2g, fc2lb,
                            fc3W, fc3b, out);
}

// round 2
// speedup vs baseline: 1.1847x; 1.1847x over previous
#include <cuda_runtime.h>
#include <math.h>
#include <float.h>

#define NN 100000
#define EE 400000
#define GG 32
#define HH 6
#define HD 192

// ---------------- scratch (device globals; no allocations allowed) ----------
__device__ float g_h[NN * HD];
__device__ float g_q[NN * HD];
__device__ float g_k[NN * HD];
__device__ float g_v[NN * HD];
__device__ float g_s[NN * HD];
__device__ float g_agg[NN * HD];
__device__ float g_m[NN * HH];
__device__ float g_z[NN * HH];
__device__ float g_p[EE * HH];
__device__ float g_pool[GG * HD];
__device__ float g_cnt[GG];

// ---------------- helpers ---------------------------------------------------
__device__ __forceinline__ void atomicMaxF(float* addr, float v) {
    if (v >= 0.0f)
        atomicMax((int*)addr, __float_as_int(v));
    else
        atomicMin((unsigned int*)addr, __float_as_uint(v));
}

__device__ __forceinline__ void redAddV4(float* addr, float4 v) {
    asm volatile("red.global.add.v4.f32 [%0], {%1,%2,%3,%4};"
                 :: "l"(addr), "f"(v.x), "f"(v.y), "f"(v.z), "f"(v.w)
                 : "memory");
}

// packed f32x2 FMA (FFMA2) — ptxas will not auto-fuse; PTX only
__device__ __forceinline__ unsigned long long fma2(unsigned long long a,
                                                   unsigned long long b,
                                                   unsigned long long c) {
    unsigned long long d;
    asm("fma.rn.f32x2 %0, %1, %2, %3;" : "=l"(d) : "l"(a), "l"(b), "l"(c));
    return d;
}
__device__ __forceinline__ unsigned long long pack2(float lo, float hi) {
    unsigned long long r;
    asm("mov.b64 %0, {%1,%2};" : "=l"(r) : "f"(lo), "f"(hi));
    return r;
}
__device__ __forceinline__ void unpack2(unsigned long long v, float& lo, float& hi) {
    asm("mov.b64 {%0,%1}, %2;" : "=f"(lo), "=f"(hi) : "l"(v));
}

// block reduce over 192 threads (6 warps)
__device__ __forceinline__ float blk_sum(float v, float* red) {
    int t = threadIdx.x, lane = t & 31, w = t >> 5;
#pragma unroll
    for (int o = 16; o; o >>= 1) v += __shfl_xor_sync(0xffffffffu, v, o);
    __syncthreads();
    if (lane == 0) red[w] = v;
    __syncthreads();
    float s = 0.f;
#pragma unroll
    for (int i = 0; i < 6; i++) s += red[i];
    return s;
}

// ---------------- input projection: h = x @ Wp + bp -------------------------
__global__ void proj_kernel(const float* __restrict__ x,
                            const float* __restrict__ Wp,
                            const float* __restrict__ bp) {
    int i = blockIdx.x * blockDim.x + threadIdx.x;
    if (i >= NN * HD) return;
    int n = i / HD, d = i - n * HD;
    const float* xr = x + n * 4;
    float acc = bp[d];
    acc += xr[0] * Wp[d] + xr[1] * Wp[HD + d] + xr[2] * Wp[2 * HD + d] + xr[3] * Wp[3 * HD + d];
    g_h[i] = acc;
}

// ---------------- fused q,k,v,skip GEMM with packed f32x2 FMA ---------------
// BM=32 rows per block, BN=192 (all cols), 4 weight matrices per block.
// 256 threads: tx = tid>>4 (col group of 12), ty = tid&15 (2 rows each).
// A tile loaded ONCE per block (shared by all 4 GEMMs).
#define BKC 16
__global__ __launch_bounds__(256) void gemm4_kernel(
    const float* __restrict__ W0, const float* __restrict__ W1,
    const float* __restrict__ W2, const float* __restrict__ W3,
    const float* __restrict__ B0, const float* __restrict__ B1,
    const float* __restrict__ B2, const float* __restrict__ B3) {
    __shared__ float sA[HD * 36];                       // sA[k*36+m], 27.6KB
    __shared__ __align__(16) float sB[BKC * HD];        // 12.3KB

    int tid = threadIdx.x;
    int ty = tid & 15, tx = tid >> 4;
    int row0 = blockIdx.x * 32;
    int m0 = ty * 2, c0 = tx * 12;

    // load + transpose A tile once (reused by all 4 weight matrices)
    for (int i = tid; i < 32 * HD; i += 256) {
        int m = i / HD, k = i - m * HD;
        sA[k * 36 + m] = g_h[(row0 + m) * HD + k];
    }

    const float* Ws_[4] = {W0, W1, W2, W3};
    const float* Bs_[4] = {B0, B1, B2, B3};
    float* Os_[4] = {g_q, g_k, g_v, g_s};

    for (int w = 0; w < 4; w++) {
        const float* W = Ws_[w];
        unsigned long long acc[2][6];
#pragma unroll
        for (int r = 0; r < 2; r++)
#pragma unroll
            for (int j = 0; j < 6; j++) acc[r][j] = pack2(0.f, 0.f);

        for (int kk = 0; kk < HD; kk += BKC) {
            __syncthreads();
            // load W chunk [BKC x 192], contiguous float4
#pragma unroll
            for (int i = 0; i < 3; i++) {
                int idx = tid * 4 + i * 1024;
                *reinterpret_cast<float4*>(&sB[idx]) =
                    *reinterpret_cast<const float4*>(&W[kk * HD + idx]);
            }
            __syncthreads();
#pragma unroll
            for (int k = 0; k < BKC; k++) {
                float2 av = *reinterpret_cast<const float2*>(&sA[(kk + k) * 36 + m0]);
                unsigned long long a0 = pack2(av.x, av.x);
                unsigned long long a1 = pack2(av.y, av.y);
                const float* br = &sB[k * HD + c0];
                float4 b0 = *reinterpret_cast<const float4*>(br);
                float4 b1 = *reinterpret_cast<const float4*>(br + 4);
                float4 b2 = *reinterpret_cast<const float4*>(br + 8);
                unsigned long long bb[6];
                bb[0] = pack2(b0.x, b0.y); bb[1] = pack2(b0.z, b0.w);
                bb[2] = pack2(b1.x, b1.y); bb[3] = pack2(b1.z, b1.w);
                bb[4] = pack2(b2.x, b2.y); bb[5] = pack2(b2.z, b2.w);
#pragma unroll
                for (int j = 0; j < 6; j++) {
                    acc[0][j] = fma2(a0, bb[j], acc[0][j]);
                    acc[1][j] = fma2(a1, bb[j], acc[1][j]);
                }
            }
        }
        // epilogue: unpack, add bias, store
        const float* Bv = Bs_[w];
        float* O = Os_[w];
#pragma unroll
        for (int r = 0; r < 2; r++) {
            int row = row0 + m0 + r;
            float out[12];
#pragma unroll
            for (int j = 0; j < 6; j++) unpack2(acc[r][j], out[2 * j], out[2 * j + 1]);
#pragma unroll
            for (int jv = 0; jv < 3; jv++) {
                float4 o;
                o.x = out[jv * 4 + 0] + Bv[c0 + jv * 4 + 0];
                o.y = out[jv * 4 + 1] + Bv[c0 + jv * 4 + 1];
                o.z = out[jv * 4 + 2] + Bv[c0 + jv * 4 + 2];
                o.w = out[jv * 4 + 3] + Bv[c0 + jv * 4 + 3];
                *reinterpret_cast<float4*>(&O[row * HD + c0 + jv * 4]) = o;
            }
        }
        __syncthreads();   // protect sB for next w (readers done)
    }
}

// ---------------- per-layer init: agg=0, z=0, m=-inf ------------------------
__global__ void init_layer_kernel() {
    int i = blockIdx.x * blockDim.x + threadIdx.x;
    if (i < NN * HD) g_agg[i] = 0.f;
    if (i < NN * HH) { g_z[i] = 0.f; g_m[i] = -FLT_MAX; }
}

// ---------------- edge logits + segment max (warp per edge) -----------------
__global__ void edge_logits_kernel(const int* __restrict__ src,
                                   const int* __restrict__ dst,
                                   const float* __restrict__ ew,
                                   const float* __restrict__ We) {
    int e = blockIdx.x * 8 + (threadIdx.x >> 5);
    int lane = threadIdx.x & 31;
    if (e >= EE) return;
    int s = src[e], d = dst[e];
    float w = ew[e];
    float acc[HH];
#pragma unroll
    for (int j = 0; j < HH; j++) {
        int dim = lane + 32 * j;
        float ke = g_k[s * HD + dim] + w * We[dim];
        acc[j] = g_q[d * HD + dim] * ke;
    }
#pragma unroll
    for (int o = 16; o; o >>= 1) {
#pragma unroll
        for (int j = 0; j < HH; j++) acc[j] += __shfl_xor_sync(0xffffffffu, acc[j], o);
    }
    const float scale = 0.17677669529663687f;  // 1/sqrt(32)
#pragma unroll
    for (int j = 0; j < HH; j++) {
        if (lane == j) {
            float lg = acc[j] * scale;
            g_p[e * HH + j] = lg;
            atomicMaxF(&g_m[d * HH + j], lg);
        }
    }
}

// ---------------- p = exp(logit - m[dst]); z += p ---------------------------
__global__ void softmax_pz_kernel(const int* __restrict__ dst) {
    int i = blockIdx.x * blockDim.x + threadIdx.x;
    if (i >= EE * HH) return;
    int e = i / HH, hh = i - e * HH;
    int d = dst[e];
    float p = expf(g_p[i] - g_m[d * HH + hh]);
    g_p[i] = p;
    atomicAdd(&g_z[d * HH + hh], p);
}

// ---------------- message aggregation (warp per edge, float4 REDs) ----------
// aggregates UNNORMALIZED p * (v+e); division by z deferred to ln_res.
__global__ void edge_agg_kernel(const int* __restrict__ src,
                                const int* __restrict__ dst,
                                const float* __restrict__ ew,
                                const float* __restrict__ We) {
    int e = blockIdx.x * 8 + (threadIdx.x >> 5);
    int lane = threadIdx.x & 31;
    if (e >= EE) return;
    int s = src[e], d = dst[e];
    float w = ew[e];
    float pv = 0.f;
    if (lane < HH) pv = g_p[e * HH + lane];
    float a0 = __shfl_sync(0xffffffffu, pv, lane >> 3);
    float a1 = __shfl_sync(0xffffffffu, pv, 4 + (lane >> 3));

    int d0 = 4 * lane;  // dims 0..127, head = lane/8
    float4 v4 = *reinterpret_cast<const float4*>(&g_v[s * HD + d0]);
    float4 w4 = *reinterpret_cast<const float4*>(&We[d0]);
    float4 msg;
    msg.x = (v4.x + w * w4.x) * a0;
    msg.y = (v4.y + w * w4.y) * a0;
    msg.z = (v4.z + w * w4.z) * a0;
    msg.w = (v4.w + w * w4.w) * a0;
    redAddV4(&g_agg[d * HD + d0], msg);

    if (lane < 16) {  // dims 128..191, head = 4 + lane/8
        int d1 = 128 + 4 * lane;
        float4 v5 = *reinterpret_cast<const float4*>(&g_v[s * HD + d1]);
        float4 w5 = *reinterpret_cast<const float4*>(&We[d1]);
        float4 m2;
        m2.x = (v5.x + w * w5.x) * a1;
        m2.y = (v5.y + w * w5.y) * a1;
        m2.z = (v5.z + w * w5.z) * a1;
        m2.w = (v5.w + w * w5.w) * a1;
        redAddV4(&g_agg[d * HD + d1], m2);
    }
}

// ---------------- hi = agg/z + skip; h += relu(LN(hi)) (warp per node) ------
__global__ void ln_res_kernel(const float* __restrict__ lg,
                              const float* __restrict__ lb) {
    int n = blockIdx.x * 8 + (threadIdx.x >> 5);
    int lane = threadIdx.x & 31;
    if (n >= NN) return;
    float v[HH];
    float s1 = 0.f;
#pragma unroll
    for (int j = 0; j < HH; j++) {
        int dim = lane + 32 * j;
        float z = g_z[n * HH + j];
        float inv = (z > 0.f) ? (1.0f / z) : 0.f;
        v[j] = g_agg[n * HD + dim] * inv + g_s[n * HD + dim];
        s1 += v[j];
    }
#pragma unroll
    for (int o = 16; o; o >>= 1) s1 += __shfl_xor_sync(0xffffffffu, s1, o);
    float mu = s1 * (1.0f / HD);
    float s2 = 0.f;
#pragma unroll
    for (int j = 0; j < HH; j++) { float dd = v[j] - mu; s2 += dd * dd; }
#pragma unroll
    for (int o = 16; o; o >>= 1) s2 += __shfl_xor_sync(0xffffffffu, s2, o);
    float rstd = rsqrtf(s2 * (1.0f / HD) + 1e-5f);
#pragma unroll
    for (int j = 0; j < HH; j++) {
        int dim = lane + 32 * j;
        float y = (v[j] - mu) * rstd * lg[dim] + lb[dim];
        g_h[n * HD + dim] += fmaxf(y, 0.f);
    }
}

// ---------------- pooling ----------------------------------------------------
__global__ void pool_init_kernel() {
    int i = blockIdx.x * blockDim.x + threadIdx.x;
    if (i < GG * HD) g_pool[i] = 0.f;
    if (i < GG) g_cnt[i] = 0.f;
}

__global__ void pool_kernel(const int* __restrict__ batch) {
    __shared__ float acc[GG * HD];
    __shared__ float scnt[GG];
    int t = threadIdx.x;  // 192
    for (int i = t; i < GG * HD; i += HD) acc[i] = 0.f;
    if (t < GG) scnt[t] = 0.f;
    __syncthreads();
    int per = (NN + gridDim.x - 1) / gridDim.x;
    int n0 = blockIdx.x * per;
    int n1 = min(n0 + per, NN);
    for (int n = n0; n < n1; n++) {
        int g = batch[n];
        acc[g * HD + t] += g_h[n * HD + t];
        if (t == 0) scnt[g] += 1.f;
    }
    __syncthreads();
    for (int i = t; i < GG * HD; i += HD) atomicAdd(&g_pool[i], acc[i]);
    if (t < GG) atomicAdd(&g_cnt[t], scnt[t]);
}

// ---------------- head MLP (block per graph, 192 threads) -------------------
__global__ void head_kernel(const float* __restrict__ ie,
                            const float* __restrict__ fciW, const float* __restrict__ fcib,
                            const float* __restrict__ fcig, const float* __restrict__ fcilb,
                            const float* __restrict__ fc1W, const float* __restrict__ fc1b,
                            const float* __restrict__ fc1g, const float* __restrict__ fc1lb,
                            const float* __restrict__ fc2W, const float* __restrict__ fc2b,
                            const float* __restrict__ fc2g, const float* __restrict__ fc2lb,
                            const float* __restrict__ fc3W, const float* __restrict__ fc3b,
                            float* __restrict__ out) {
    __shared__ float zin[2 * HD];
    __shared__ float buf[HD];
    __shared__ float red[8];
    int t = threadIdx.x;  // 0..191
    int g = blockIdx.x;

    float cnt = fmaxf(g_cnt[g], 1.f);
    zin[t] = g_pool[g * HD + t] / cnt;

    // fc_initial: Linear(1,192) + LN + ReLU
    float iv = ie[g] * fciW[t] + fcib[t];
    float mu = blk_sum(iv, red) * (1.0f / HD);
    float dv = iv - mu;
    float var = blk_sum(dv * dv, red) * (1.0f / HD);
    float rstd = rsqrtf(var + 1e-5f);
    zin[HD + t] = fmaxf(dv * rstd * fcig[t] + fcilb[t], 0.f);
    __syncthreads();

    // fc1: 384 -> 192, LN, ReLU
    float a = fc1b[t];
    for (int k = 0; k < 2 * HD; k++) a += zin[k] * fc1W[k * HD + t];
    mu = blk_sum(a, red) * (1.0f / HD);
    dv = a - mu;
    var = blk_sum(dv * dv, red) * (1.0f / HD);
    rstd = rsqrtf(var + 1e-5f);
    buf[t] = fmaxf(dv * rstd * fc1g[t] + fc1lb[t], 0.f);
    __syncthreads();

    // fc2: 192 -> 96, LN, ReLU
    float a2 = 0.f;
    if (t < 96) {
        a2 = fc2b[t];
        for (int k = 0; k < HD; k++) a2 += buf[k] * fc2W[k * 96 + t];
    }
    mu = blk_sum(t < 96 ? a2 : 0.f, red) * (1.0f / 96.0f);
    dv = a2 - mu;
    var = blk_sum(t < 96 ? dv * dv : 0.f, red) * (1.0f / 96.0f);
    rstd = rsqrtf(var + 1e-5f);
    float r2 = 0.f;
    if (t < 96) r2 = fmaxf(dv * rstd * fc2g[t] + fc2lb[t], 0.f);

    // fc3: 96 -> 1
    float p3 = (t < 96) ? r2 * fc3W[t] : 0.f;
    float tot = blk_sum(p3, red);
    if (t == 0) out[g] = tot + fc3b[0];
}

// ---------------- launch ------------------------------------------------------
extern "C" void kernel_launch(void* const* d_in, const int* in_sizes, int n_in,
                              void* d_out, int out_size) {
    const float* x    = (const float*)d_in[0];
    const int*   ei   = (const int*)d_in[1];
    const float* ew   = (const float*)d_in[2];
    const int*   batch= (const int*)d_in[3];
    const float* ie   = (const float*)d_in[4];
    const float* Wp   = (const float*)d_in[5];
    const float* bp   = (const float*)d_in[6];
    const float* Wq   = (const float*)d_in[7];
    const float* bq   = (const float*)d_in[8];
    const float* Wk   = (const float*)d_in[9];
    const float* bk   = (const float*)d_in[10];
    const float* Wv   = (const float*)d_in[11];
    const float* bv   = (const float*)d_in[12];
    const float* We   = (const float*)d_in[13];
    const float* Ws   = (const float*)d_in[14];
    const float* bs   = (const float*)d_in[15];
    const float* lng  = (const float*)d_in[16];
    const float* lnb  = (const float*)d_in[17];
    const float* fciW = (const float*)d_in[18];
    const float* fcib = (const float*)d_in[19];
    const float* fcig = (const float*)d_in[20];
    const float* fcilb= (const float*)d_in[21];
    const float* fc1W = (const float*)d_in[22];
    const float* fc1b = (const float*)d_in[23];
    const float* fc1g = (const float*)d_in[24];
    const float* fc1lb= (const float*)d_in[25];
    const float* fc2W = (const float*)d_in[26];
    const float* fc2b = (const float*)d_in[27];
    const float* fc2g = (const float*)d_in[28];
    const float* fc2lb= (const float*)d_in[29];
    const float* fc3W = (const float*)d_in[30];
    const float* fc3b = (const float*)d_in[31];
    float* out = (float*)d_out;

    const int* src = ei;
    const int* dst = ei + EE;

    proj_kernel<<<(NN * HD + 255) / 256, 256>>>(x, Wp, bp);

    for (int i = 0; i < 3; i++) {
        gemm4_kernel<<<NN / 32, 256>>>(
            Wq + i * HD * HD, Wk + i * HD * HD, Wv + i * HD * HD, Ws + i * HD * HD,
            bq + i * HD, bk + i * HD, bv + i * HD, bs + i * HD);
        init_layer_kernel<<<(NN * HD + 255) / 256, 256>>>();
        edge_logits_kernel<<<EE / 8, 256>>>(src, dst, ew, We + i * HD);
        softmax_pz_kernel<<<(EE * HH + 255) / 256, 256>>>(dst);
        edge_agg_kernel<<<EE / 8, 256>>>(src, dst, ew, We + i * HD);
        ln_res_kernel<<<NN / 8, 256>>>(lng + i * HD, lnb + i * HD);
    }

    pool_init_kernel<<<(GG * HD + 255) / 256, 256>>>();
    pool_kernel<<<512, HD>>>(batch);
    head_kernel<<<GG, HD>>>(ie, fciW, fcib, fcig, fcilb,
                            fc1W, fc1b, fc1g, fc1lb,
                            fc2W, fc2b, fc2g, fc2lb,
                            fc3W, fc3b, out);
}

// round 3
// speedup vs baseline: 1.7029x; 1.4375x over previous
#include <cuda_runtime.h>
#include <cuda_bf16.h>
#include <math.h>
#include <float.h>

#define NN 100000
#define EE 400000
#define GG 32
#define HH 6
#define HD 192
#define NTILES 6256          // ceil(100000/16) padded to multiple of 8 -> 6250 -> 6256
#define KSTEPS 12            // 192/16

// ---------------- scratch (device globals; no allocations allowed) ----------
__device__ float g_h[NN * HD];
__device__ float g_q[NN * HD];
__device__ float g_k[NN * HD];
__device__ float g_v[NN * HD];
__device__ float g_s[NN * HD];
__device__ float g_agg[NN * HD];
__device__ float g_m[NN * HH];
__device__ float g_z[NN * HH];
__device__ float g_p[EE * HH];
__device__ float g_pool[GG * HD];
__device__ float g_cnt[GG];

// fragment-layout operands for mma.sync (hi bf16x2 in low u32, lo in high u32)
__device__ unsigned long long g_afrag[(size_t)NTILES * KSTEPS * 4 * 32];      // 77MB
__device__ unsigned long long g_wfrag[(size_t)12 * KSTEPS * 24 * 2 * 32];     // 1.77MB

// ---------------- helpers ---------------------------------------------------
__device__ __forceinline__ void atomicMaxF(float* addr, float v) {
    if (v >= 0.0f)
        atomicMax((int*)addr, __float_as_int(v));
    else
        atomicMin((unsigned int*)addr, __float_as_uint(v));
}

__device__ __forceinline__ void redAddV4(float* addr, float4 v) {
    asm volatile("red.global.add.v4.f32 [%0], {%1,%2,%3,%4};"
                 :: "l"(addr), "f"(v.x), "f"(v.y), "f"(v.z), "f"(v.w)
                 : "memory");
}

// round-to-nearest-even bf16 truncation, returned as fp32 value
__device__ __forceinline__ float bf_hi(float x) {
    unsigned u = __float_as_uint(x);
    unsigned r = (u + 0x7fffu + ((u >> 16) & 1u)) & 0xffff0000u;
    return __uint_as_float(r);
}
// pack two floats as bf16x2 (a -> low half, b -> high half), rn
__device__ __forceinline__ unsigned bf2(float a, float b) {
    unsigned r;
    asm("cvt.rn.bf16x2.f32 %0, %1, %2;" : "=r"(r) : "f"(b), "f"(a));
    return r;
}

__device__ __forceinline__ void mma_bf16(float* c, const unsigned* a, const unsigned* b) {
    asm("mma.sync.aligned.m16n8k16.row.col.f32.bf16.bf16.f32 "
        "{%0,%1,%2,%3}, {%4,%5,%6,%7}, {%8,%9}, {%0,%1,%2,%3};"
        : "+f"(c[0]), "+f"(c[1]), "+f"(c[2]), "+f"(c[3])
        : "r"(a[0]), "r"(a[1]), "r"(a[2]), "r"(a[3]), "r"(b[0]), "r"(b[1]));
}

// block reduce over 192 threads (6 warps)
__device__ __forceinline__ float blk_sum(float v, float* red) {
    int t = threadIdx.x, lane = t & 31, w = t >> 5;
#pragma unroll
    for (int o = 16; o; o >>= 1) v += __shfl_xor_sync(0xffffffffu, v, o);
    __syncthreads();
    if (lane == 0) red[w] = v;
    __syncthreads();
    float s = 0.f;
#pragma unroll
    for (int i = 0; i < 6; i++) s += red[i];
    return s;
}

// ---------------- input projection: h = x @ Wp + bp -------------------------
__global__ void proj_kernel(const float* __restrict__ x,
                            const float* __restrict__ Wp,
                            const float* __restrict__ bp) {
    int i = blockIdx.x * blockDim.x + threadIdx.x;
    if (i >= NN * HD) return;
    int n = i / HD, d = i - n * HD;
    const float* xr = x + n * 4;
    float acc = bp[d];
    acc += xr[0] * Wp[d] + xr[1] * Wp[HD + d] + xr[2] * Wp[2 * HD + d] + xr[3] * Wp[3 * HD + d];
    g_h[i] = acc;
}

// ---------------- split h into A-fragment layout (hi/lo bf16) ---------------
// t enumerates (((tile*12+ks)*4+reg)*32+lane); coalesced u64 writes.
__global__ void split_h_kernel() {
    int t = blockIdx.x * 256 + threadIdx.x;
    int lane = t & 31;
    int reg = (t >> 5) & 3;
    int ks = (t >> 7) % KSTEPS;
    int tile = t / (KSTEPS * 4 * 32);
    int row = tile * 16 + (lane >> 2) + ((reg & 1) << 3);
    int k = ks * 16 + ((lane & 3) << 1) + ((reg >> 1) << 3);
    float x0 = 0.f, x1 = 0.f;
    if (row < NN) {
        const float* p = &g_h[row * HD + k];
        x0 = p[0]; x1 = p[1];
    }
    float h0 = bf_hi(x0), h1 = bf_hi(x1);
    unsigned hi = bf2(h0, h1);
    unsigned lo = bf2(x0 - h0, x1 - h1);
    g_afrag[t] = ((unsigned long long)lo << 32) | hi;
}

// ---------------- split all 12 weight matrices into B-fragment layout -------
__global__ void split_w_kernel(const float* __restrict__ Wq, const float* __restrict__ Wk,
                               const float* __restrict__ Wv, const float* __restrict__ Ws) {
    int t = blockIdx.x * 256 + threadIdx.x;
    int lane = t & 31;
    int reg = (t >> 5) & 1;
    int nt = (t >> 6) % 24;
    int ks = ((t >> 6) / 24) % KSTEPS;
    int mat = t / (32 * 2 * 24 * KSTEPS);
    int n = nt * 8 + (lane >> 2);
    int k = ks * 16 + ((lane & 3) << 1) + (reg << 3);
    int which = mat & 3, layer = mat >> 2;
    const float* W = (which == 0 ? Wq : which == 1 ? Wk : which == 2 ? Wv : Ws)
                     + (size_t)layer * HD * HD;
    float w0 = W[k * HD + n];
    float w1 = W[(k + 1) * HD + n];
    float h0 = bf_hi(w0), h1 = bf_hi(w1);
    unsigned hi = bf2(h0, h1);
    unsigned lo = bf2(w0 - h0, w1 - h1);
    g_wfrag[t] = ((unsigned long long)lo << 32) | hi;
}

// ---------------- tensor-core GEMM: O = h @ W + b, 3-pass bf16 split --------
// CTA: 256 thr = 8 warps. warp (wm 0..1, wn 0..3): m64 x n48 tile.
// CTA tile: m128 x n192. grid = (NTILES/8=782, 4 matrices).
__global__ __launch_bounds__(256) void gemm_tc_kernel(
    int layer,
    const float* __restrict__ bq, const float* __restrict__ bk,
    const float* __restrict__ bv, const float* __restrict__ bs) {
    int w = threadIdx.x >> 5, lane = threadIdx.x & 31;
    int wm = w & 1, wn = w >> 1;
    int tile0 = blockIdx.x * 8 + wm * 4;
    int mat = layer * 4 + blockIdx.y;

    float C[4][6][4];
#pragma unroll
    for (int mt = 0; mt < 4; mt++)
#pragma unroll
        for (int nt = 0; nt < 6; nt++)
#pragma unroll
            for (int i = 0; i < 4; i++) C[mt][nt][i] = 0.f;

    const unsigned long long* __restrict__ A = g_afrag;
    const unsigned long long* __restrict__ B =
        g_wfrag + (size_t)mat * KSTEPS * 24 * 2 * 32;

#pragma unroll 2
    for (int ks = 0; ks < KSTEPS; ks++) {
        unsigned ah[4][4], al[4][4];
#pragma unroll
        for (int mt = 0; mt < 4; mt++) {
            size_t base = (((size_t)(tile0 + mt) * KSTEPS + ks) * 4) * 32 + lane;
#pragma unroll
            for (int r = 0; r < 4; r++) {
                unsigned long long v = __ldg(&A[base + r * 32]);
                ah[mt][r] = (unsigned)v;
                al[mt][r] = (unsigned)(v >> 32);
            }
        }
#pragma unroll
        for (int nt = 0; nt < 6; nt++) {
            int ntg = wn * 6 + nt;
            size_t bb = (((size_t)ks * 24 + ntg) * 2) * 32 + lane;
            unsigned bh[2], bl[2];
#pragma unroll
            for (int r = 0; r < 2; r++) {
                unsigned long long v = __ldg(&B[bb + r * 32]);
                bh[r] = (unsigned)v;
                bl[r] = (unsigned)(v >> 32);
            }
#pragma unroll
            for (int mt = 0; mt < 4; mt++) {
                mma_bf16(C[mt][nt], ah[mt], bh);
                mma_bf16(C[mt][nt], ah[mt], bl);
                mma_bf16(C[mt][nt], al[mt], bh);
            }
        }
    }

    float* O = (blockIdx.y == 0) ? g_q : (blockIdx.y == 1) ? g_k
             : (blockIdx.y == 2) ? g_v : g_s;
    const float* Bv = ((blockIdx.y == 0) ? bq : (blockIdx.y == 1) ? bk
                     : (blockIdx.y == 2) ? bv : bs) + layer * HD;
#pragma unroll
    for (int mt = 0; mt < 4; mt++) {
        int r0 = (tile0 + mt) * 16 + (lane >> 2);
#pragma unroll
        for (int nt = 0; nt < 6; nt++) {
            int c = (wn * 6 + nt) * 8 + (lane & 3) * 2;
            float b0 = Bv[c], b1 = Bv[c + 1];
            if (r0 < NN) {
                float2 o = {C[mt][nt][0] + b0, C[mt][nt][1] + b1};
                *reinterpret_cast<float2*>(&O[r0 * HD + c]) = o;
            }
            int r1 = r0 + 8;
            if (r1 < NN) {
                float2 o = {C[mt][nt][2] + b0, C[mt][nt][3] + b1};
                *reinterpret_cast<float2*>(&O[r1 * HD + c]) = o;
            }
        }
    }
}

// ---------------- per-layer init: agg=0, z=0, m=-inf ------------------------
__global__ void init_layer_kernel() {
    int i = blockIdx.x * blockDim.x + threadIdx.x;
    if (i < NN * HD) g_agg[i] = 0.f;
    if (i < NN * HH) { g_z[i] = 0.f; g_m[i] = -FLT_MAX; }
}

// ---------------- edge logits + segment max (warp per edge) -----------------
__global__ void edge_logits_kernel(const int* __restrict__ src,
                                   const int* __restrict__ dst,
                                   const float* __restrict__ ew,
                                   const float* __restrict__ We) {
    int e = blockIdx.x * 8 + (threadIdx.x >> 5);
    int lane = threadIdx.x & 31;
    if (e >= EE) return;
    int s = src[e], d = dst[e];
    float w = ew[e];
    float acc[HH];
#pragma unroll
    for (int j = 0; j < HH; j++) {
        int dim = lane + 32 * j;
        float ke = g_k[s * HD + dim] + w * We[dim];
        acc[j] = g_q[d * HD + dim] * ke;
    }
#pragma unroll
    for (int o = 16; o; o >>= 1) {
#pragma unroll
        for (int j = 0; j < HH; j++) acc[j] += __shfl_xor_sync(0xffffffffu, acc[j], o);
    }
    const float scale = 0.17677669529663687f;  // 1/sqrt(32)
#pragma unroll
    for (int j = 0; j < HH; j++) {
        if (lane == j) {
            float lg = acc[j] * scale;
            g_p[e * HH + j] = lg;
            atomicMaxF(&g_m[d * HH + j], lg);
        }
    }
}

// ---------------- p = exp(logit - m[dst]); z += p ---------------------------
__global__ void softmax_pz_kernel(const int* __restrict__ dst) {
    int i = blockIdx.x * blockDim.x + threadIdx.x;
    if (i >= EE * HH) return;
    int e = i / HH, hh = i - e * HH;
    int d = dst[e];
    float p = expf(g_p[i] - g_m[d * HH + hh]);
    g_p[i] = p;
    atomicAdd(&g_z[d * HH + hh], p);
}

// ---------------- message aggregation (warp per edge, float4 REDs) ----------
// aggregates UNNORMALIZED p * (v+e); division by z deferred to ln_res.
__global__ void edge_agg_kernel(const int* __restrict__ src,
                                const int* __restrict__ dst,
                                const float* __restrict__ ew,
                                const float* __restrict__ We) {
    int e = blockIdx.x * 8 + (threadIdx.x >> 5);
    int lane = threadIdx.x & 31;
    if (e >= EE) return;
    int s = src[e], d = dst[e];
    float w = ew[e];
    float pv = 0.f;
    if (lane < HH) pv = g_p[e * HH + lane];
    float a0 = __shfl_sync(0xffffffffu, pv, lane >> 3);
    float a1 = __shfl_sync(0xffffffffu, pv, 4 + (lane >> 3));

    int d0 = 4 * lane;  // dims 0..127, head = lane/8
    float4 v4 = *reinterpret_cast<const float4*>(&g_v[s * HD + d0]);
    float4 w4 = *reinterpret_cast<const float4*>(&We[d0]);
    float4 msg;
    msg.x = (v4.x + w * w4.x) * a0;
    msg.y = (v4.y + w * w4.y) * a0;
    msg.z = (v4.z + w * w4.z) * a0;
    msg.w = (v4.w + w * w4.w) * a0;
    redAddV4(&g_agg[d * HD + d0], msg);

    if (lane < 16) {  // dims 128..191, head = 4 + lane/8
        int d1 = 128 + 4 * lane;
        float4 v5 = *reinterpret_cast<const float4*>(&g_v[s * HD + d1]);
        float4 w5 = *reinterpret_cast<const float4*>(&We[d1]);
        float4 m2;
        m2.x = (v5.x + w * w5.x) * a1;
        m2.y = (v5.y + w * w5.y) * a1;
        m2.z = (v5.z + w * w5.z) * a1;
        m2.w = (v5.w + w * w5.w) * a1;
        redAddV4(&g_agg[d * HD + d1], m2);
    }
}

// ---------------- hi = agg/z + skip; h += relu(LN(hi)) (warp per node) ------
__global__ void ln_res_kernel(const float* __restrict__ lg,
                              const float* __restrict__ lb) {
    int n = blockIdx.x * 8 + (threadIdx.x >> 5);
    int lane = threadIdx.x & 31;
    if (n >= NN) return;
    float v[HH];
    float s1 = 0.f;
#pragma unroll
    for (int j = 0; j < HH; j++) {
        int dim = lane + 32 * j;
        float z = g_z[n * HH + j];
        float inv = (z > 0.f) ? (1.0f / z) : 0.f;
        v[j] = g_agg[n * HD + dim] * inv + g_s[n * HD + dim];
        s1 += v[j];
    }
#pragma unroll
    for (int o = 16; o; o >>= 1) s1 += __shfl_xor_sync(0xffffffffu, s1, o);
    float mu = s1 * (1.0f / HD);
    float s2 = 0.f;
#pragma unroll
    for (int j = 0; j < HH; j++) { float dd = v[j] - mu; s2 += dd * dd; }
#pragma unroll
    for (int o = 16; o; o >>= 1) s2 += __shfl_xor_sync(0xffffffffu, s2, o);
    float rstd = rsqrtf(s2 * (1.0f / HD) + 1e-5f);
#pragma unroll
    for (int j = 0; j < HH; j++) {
        int dim = lane + 32 * j;
        float y = (v[j] - mu) * rstd * lg[dim] + lb[dim];
        g_h[n * HD + dim] += fmaxf(y, 0.f);
    }
}

// ---------------- pooling ----------------------------------------------------
__global__ void pool_init_kernel() {
    int i = blockIdx.x * blockDim.x + threadIdx.x;
    if (i < GG * HD) g_pool[i] = 0.f;
    if (i < GG) g_cnt[i] = 0.f;
}

__global__ void pool_kernel(const int* __restrict__ batch) {
    __shared__ float acc[GG * HD];
    __shared__ float scnt[GG];
    int t = threadIdx.x;  // 192
    for (int i = t; i < GG * HD; i += HD) acc[i] = 0.f;
    if (t < GG) scnt[t] = 0.f;
    __syncthreads();
    int per = (NN + gridDim.x - 1) / gridDim.x;
    int n0 = blockIdx.x * per;
    int n1 = min(n0 + per, NN);
    for (int n = n0; n < n1; n++) {
        int g = batch[n];
        acc[g * HD + t] += g_h[n * HD + t];
        if (t == 0) scnt[g] += 1.f;
    }
    __syncthreads();
    for (int i = t; i < GG * HD; i += HD) atomicAdd(&g_pool[i], acc[i]);
    if (t < GG) atomicAdd(&g_cnt[t], scnt[t]);
}

// ---------------- head MLP (block per graph, 192 threads) -------------------
__global__ void head_kernel(const float* __restrict__ ie,
                            const float* __restrict__ fciW, const float* __restrict__ fcib,
                            const float* __restrict__ fcig, const float* __restrict__ fcilb,
                            const float* __restrict__ fc1W, const float* __restrict__ fc1b,
                            const float* __restrict__ fc1g, const float* __restrict__ fc1lb,
                            const float* __restrict__ fc2W, const float* __restrict__ fc2b,
                            const float* __restrict__ fc2g, const float* __restrict__ fc2lb,
                            const float* __restrict__ fc3W, const float* __restrict__ fc3b,
                            float* __restrict__ out) {
    __shared__ float zin[2 * HD];
    __shared__ float buf[HD];
    __shared__ float red[8];
    int t = threadIdx.x;  // 0..191
    int g = blockIdx.x;

    float cnt = fmaxf(g_cnt[g], 1.f);
    zin[t] = g_pool[g * HD + t] / cnt;

    // fc_initial: Linear(1,192) + LN + ReLU
    float iv = ie[g] * fciW[t] + fcib[t];
    float mu = blk_sum(iv, red) * (1.0f / HD);
    float dv = iv - mu;
    float var = blk_sum(dv * dv, red) * (1.0f / HD);
    float rstd = rsqrtf(var + 1e-5f);
    zin[HD + t] = fmaxf(dv * rstd * fcig[t] + fcilb[t], 0.f);
    __syncthreads();

    // fc1: 384 -> 192, LN, ReLU
    float a = fc1b[t];
    for (int k = 0; k < 2 * HD; k++) a += zin[k] * fc1W[k * HD + t];
    mu = blk_sum(a, red) * (1.0f / HD);
    dv = a - mu;
    var = blk_sum(dv * dv, red) * (1.0f / HD);
    rstd = rsqrtf(var + 1e-5f);
    buf[t] = fmaxf(dv * rstd * fc1g[t] + fc1lb[t], 0.f);
    __syncthreads();

    // fc2: 192 -> 96, LN, ReLU
    float a2 = 0.f;
    if (t < 96) {
        a2 = fc2b[t];
        for (int k = 0; k < HD; k++) a2 += buf[k] * fc2W[k * 96 + t];
    }
    mu = blk_sum(t < 96 ? a2 : 0.f, red) * (1.0f / 96.0f);
    dv = a2 - mu;
    var = blk_sum(t < 96 ? dv * dv : 0.f, red) * (1.0f / 96.0f);
    rstd = rsqrtf(var + 1e-5f);
    float r2 = 0.f;
    if (t < 96) r2 = fmaxf(dv * rstd * fc2g[t] + fc2lb[t], 0.f);

    // fc3: 96 -> 1
    float p3 = (t < 96) ? r2 * fc3W[t] : 0.f;
    float tot = blk_sum(p3, red);
    if (t == 0) out[g] = tot + fc3b[0];
}

// ---------------- launch ------------------------------------------------------
extern "C" void kernel_launch(void* const* d_in, const int* in_sizes, int n_in,
                              void* d_out, int out_size) {
    const float* x    = (const float*)d_in[0];
    const int*   ei   = (const int*)d_in[1];
    const float* ew   = (const float*)d_in[2];
    const int*   batch= (const int*)d_in[3];
    const float* ie   = (const float*)d_in[4];
    const float* Wp   = (const float*)d_in[5];
    const float* bp   = (const float*)d_in[6];
    const float* Wq   = (const float*)d_in[7];
    const float* bq   = (const float*)d_in[8];
    const float* Wk   = (const float*)d_in[9];
    const float* bk   = (const float*)d_in[10];
    const float* Wv   = (const float*)d_in[11];
    const float* bv   = (const float*)d_in[12];
    const float* We   = (const float*)d_in[13];
    const float* Ws   = (const float*)d_in[14];
    const float* bs   = (const float*)d_in[15];
    const float* lng  = (const float*)d_in[16];
    const float* lnb  = (const float*)d_in[17];
    const float* fciW = (const float*)d_in[18];
    const float* fcib = (const float*)d_in[19];
    const float* fcig = (const float*)d_in[20];
    const float* fcilb= (const float*)d_in[21];
    const float* fc1W = (const float*)d_in[22];
    const float* fc1b = (const float*)d_in[23];
    const float* fc1g = (const float*)d_in[24];
    const float* fc1lb= (const float*)d_in[25];
    const float* fc2W = (const float*)d_in[26];
    const float* fc2b = (const float*)d_in[27];
    const float* fc2g = (const float*)d_in[28];
    const float* fc2lb= (const float*)d_in[29];
    const float* fc3W = (const float*)d_in[30];
    const float* fc3b = (const float*)d_in[31];
    float* out = (float*)d_out;

    const int* src = ei;
    const int* dst = ei + EE;

    proj_kernel<<<(NN * HD + 255) / 256, 256>>>(x, Wp, bp);
    split_w_kernel<<<864, 256>>>(Wq, Wk, Wv, Ws);   // 12*12*24*2*32 / 256

    for (int i = 0; i < 3; i++) {
        split_h_kernel<<<NTILES * KSTEPS * 4 * 32 / 256, 256>>>();
        gemm_tc_kernel<<<dim3(NTILES / 8, 4), 256>>>(i, bq, bk, bv, bs);
        init_layer_kernel<<<(NN * HD + 255) / 256, 256>>>();
        edge_logits_kernel<<<EE / 8, 256>>>(src, dst, ew, We + i * HD);
        softmax_pz_kernel<<<(EE * HH + 255) / 256, 256>>>(dst);
        edge_agg_kernel<<<EE / 8, 256>>>(src, dst, ew, We + i * HD);
        ln_res_kernel<<<NN / 8, 256>>>(lng + i * HD, lnb + i * HD);
    }

    pool_init_kernel<<<(GG * HD + 255) / 256, 256>>>();
    pool_kernel<<<512, HD>>>(batch);
    head_kernel<<<GG, HD>>>(ie, fciW, fcib, fcig, fcilb,
                            fc1W, fc1b, fc1g, fc1lb,
                            fc2W, fc2b, fc2g, fc2lb,
                            fc3W, fc3b, out);
}

// round 4
// speedup vs baseline: 1.7479x; 1.0264x over previous
#include <cuda_runtime.h>
#include <cuda_bf16.h>
#include <math.h>
#include <float.h>

#define NN 100000
#define EE 400000
#define GG 32
#define HH 6
#define HD 192
#define NTILES 6256          // ceil(100000/16)=6250, padded to multiple of 8
#define KSTEPS 12            // 192/16

// ---------------- scratch (device globals; no allocations allowed) ----------
__device__ float g_h[NN * HD];
__device__ float g_q[NN * HD];
__device__ float g_k[NN * HD];
__device__ float g_v[NN * HD];
__device__ float g_s[NN * HD];
__device__ float g_agg[NN * HD];
__device__ float g_m[NN * HH];
__device__ float g_z[NN * HH];
__device__ float g_p[EE * HH];
__device__ float g_pool[GG * HD];
__device__ float g_cnt[GG];

// fragment-layout operands for mma.sync (hi bf16x2 in low u32, lo in high u32)
__device__ unsigned long long g_afrag[(size_t)NTILES * KSTEPS * 4 * 32];      // 77MB
__device__ unsigned long long g_wfrag[(size_t)12 * KSTEPS * 24 * 2 * 32];     // 1.77MB

// ---------------- helpers ---------------------------------------------------
__device__ __forceinline__ void atomicMaxF(float* addr, float v) {
    if (v >= 0.0f)
        atomicMax((int*)addr, __float_as_int(v));
    else
        atomicMin((unsigned int*)addr, __float_as_uint(v));
}

__device__ __forceinline__ void redAddV4(float* addr, float4 v) {
    asm volatile("red.global.add.v4.f32 [%0], {%1,%2,%3,%4};"
                 :: "l"(addr), "f"(v.x), "f"(v.y), "f"(v.z), "f"(v.w)
                 : "memory");
}

// round-to-nearest-even bf16 truncation, returned as fp32 value
__device__ __forceinline__ float bf_hi(float x) {
    unsigned u = __float_as_uint(x);
    unsigned r = (u + 0x7fffu + ((u >> 16) & 1u)) & 0xffff0000u;
    return __uint_as_float(r);
}
// pack two floats as bf16x2 (a -> low half, b -> high half), rn
__device__ __forceinline__ unsigned bf2(float a, float b) {
    unsigned r;
    asm("cvt.rn.bf16x2.f32 %0, %1, %2;" : "=r"(r) : "f"(b), "f"(a));
    return r;
}

__device__ __forceinline__ void mma_bf16(float* c, const unsigned* a, const unsigned* b) {
    asm("mma.sync.aligned.m16n8k16.row.col.f32.bf16.bf16.f32 "
        "{%0,%1,%2,%3}, {%4,%5,%6,%7}, {%8,%9}, {%0,%1,%2,%3};"
        : "+f"(c[0]), "+f"(c[1]), "+f"(c[2]), "+f"(c[3])
        : "r"(a[0]), "r"(a[1]), "r"(a[2]), "r"(a[3]), "r"(b[0]), "r"(b[1]));
}

// block reduce over 192 threads (6 warps)
__device__ __forceinline__ float blk_sum(float v, float* red) {
    int t = threadIdx.x, lane = t & 31, w = t >> 5;
#pragma unroll
    for (int o = 16; o; o >>= 1) v += __shfl_xor_sync(0xffffffffu, v, o);
    __syncthreads();
    if (lane == 0) red[w] = v;
    __syncthreads();
    float s = 0.f;
#pragma unroll
    for (int i = 0; i < 6; i++) s += red[i];
    return s;
}

// ---------------- input projection: h = x @ Wp + bp -------------------------
__global__ void proj_kernel(const float* __restrict__ x,
                            const float* __restrict__ Wp,
                            const float* __restrict__ bp) {
    int i = blockIdx.x * blockDim.x + threadIdx.x;
    if (i >= NN * HD) return;
    int n = i / HD, d = i - n * HD;
    const float* xr = x + n * 4;
    float acc = bp[d];
    acc += xr[0] * Wp[d] + xr[1] * Wp[HD + d] + xr[2] * Wp[2 * HD + d] + xr[3] * Wp[3 * HD + d];
    g_h[i] = acc;
}

// ---------------- split h into A-fragment layout (hi/lo bf16) ---------------
__global__ void split_h_kernel() {
    int t = blockIdx.x * 256 + threadIdx.x;
    int lane = t & 31;
    int reg = (t >> 5) & 3;
    int ks = (t >> 7) % KSTEPS;
    int tile = t / (KSTEPS * 4 * 32);
    int row = tile * 16 + (lane >> 2) + ((reg & 1) << 3);
    int k = ks * 16 + ((lane & 3) << 1) + ((reg >> 1) << 3);
    float x0 = 0.f, x1 = 0.f;
    if (row < NN) {
        const float* p = &g_h[row * HD + k];
        x0 = p[0]; x1 = p[1];
    }
    float h0 = bf_hi(x0), h1 = bf_hi(x1);
    unsigned hi = bf2(h0, h1);
    unsigned lo = bf2(x0 - h0, x1 - h1);
    g_afrag[t] = ((unsigned long long)lo << 32) | hi;
}

// ---------------- split all 12 weight matrices into B-fragment layout -------
__global__ void split_w_kernel(const float* __restrict__ Wq, const float* __restrict__ Wk,
                               const float* __restrict__ Wv, const float* __restrict__ Ws) {
    int t = blockIdx.x * 256 + threadIdx.x;
    int lane = t & 31;
    int reg = (t >> 5) & 1;
    int nt = (t >> 6) % 24;
    int ks = ((t >> 6) / 24) % KSTEPS;
    int mat = t / (32 * 2 * 24 * KSTEPS);
    int n = nt * 8 + (lane >> 2);
    int k = ks * 16 + ((lane & 3) << 1) + (reg << 3);
    int which = mat & 3, layer = mat >> 2;
    const float* W = (which == 0 ? Wq : which == 1 ? Wk : which == 2 ? Wv : Ws)
                     + (size_t)layer * HD * HD;
    float w0 = W[k * HD + n];
    float w1 = W[(k + 1) * HD + n];
    float h0 = bf_hi(w0), h1 = bf_hi(w1);
    unsigned hi = bf2(h0, h1);
    unsigned lo = bf2(w0 - h0, w1 - h1);
    g_wfrag[t] = ((unsigned long long)lo << 32) | hi;
}

// ---------------- tensor-core GEMM: O = h @ W + b, 3-pass bf16 split --------
// CTA: 256 thr = 8 warps, 2 CTAs/SM. warp (wm 0..1, wn 0..3): m32 x n48 tile.
// CTA tile: m64 x n192. grid = (NTILES/4, 4 matrices).
__global__ __launch_bounds__(256, 2) void gemm_tc_kernel(
    int layer,
    const float* __restrict__ bq, const float* __restrict__ bk,
    const float* __restrict__ bv, const float* __restrict__ bs) {
    int w = threadIdx.x >> 5, lane = threadIdx.x & 31;
    int wm = w & 1, wn = w >> 1;
    int tile0 = blockIdx.x * 4 + wm * 2;
    int mat = layer * 4 + blockIdx.y;

    float C[2][6][4];
#pragma unroll
    for (int mt = 0; mt < 2; mt++)
#pragma unroll
        for (int nt = 0; nt < 6; nt++)
#pragma unroll
            for (int i = 0; i < 4; i++) C[mt][nt][i] = 0.f;

    const unsigned long long* __restrict__ A = g_afrag;
    const unsigned long long* __restrict__ B =
        g_wfrag + (size_t)mat * KSTEPS * 24 * 2 * 32;

#pragma unroll 2
    for (int ks = 0; ks < KSTEPS; ks++) {
        unsigned ah[2][4], al[2][4];
#pragma unroll
        for (int mt = 0; mt < 2; mt++) {
            size_t base = (((size_t)(tile0 + mt) * KSTEPS + ks) * 4) * 32 + lane;
#pragma unroll
            for (int r = 0; r < 4; r++) {
                unsigned long long v = __ldg(&A[base + r * 32]);
                ah[mt][r] = (unsigned)v;
                al[mt][r] = (unsigned)(v >> 32);
            }
        }
#pragma unroll
        for (int nt = 0; nt < 6; nt++) {
            int ntg = wn * 6 + nt;
            size_t bb = (((size_t)ks * 24 + ntg) * 2) * 32 + lane;
            unsigned bh[2], bl[2];
#pragma unroll
            for (int r = 0; r < 2; r++) {
                unsigned long long v = __ldg(&B[bb + r * 32]);
                bh[r] = (unsigned)v;
                bl[r] = (unsigned)(v >> 32);
            }
#pragma unroll
            for (int mt = 0; mt < 2; mt++) {
                mma_bf16(C[mt][nt], ah[mt], bh);
                mma_bf16(C[mt][nt], ah[mt], bl);
                mma_bf16(C[mt][nt], al[mt], bh);
            }
        }
    }

    float* O = (blockIdx.y == 0) ? g_q : (blockIdx.y == 1) ? g_k
             : (blockIdx.y == 2) ? g_v : g_s;
    const float* Bv = ((blockIdx.y == 0) ? bq : (blockIdx.y == 1) ? bk
                     : (blockIdx.y == 2) ? bv : bs) + layer * HD;
#pragma unroll
    for (int mt = 0; mt < 2; mt++) {
        int r0 = (tile0 + mt) * 16 + (lane >> 2);
#pragma unroll
        for (int nt = 0; nt < 6; nt++) {
            int c = (wn * 6 + nt) * 8 + (lane & 3) * 2;
            float b0 = Bv[c], b1 = Bv[c + 1];
            if (r0 < NN) {
                float2 o = {C[mt][nt][0] + b0, C[mt][nt][1] + b1};
                *reinterpret_cast<float2*>(&O[r0 * HD + c]) = o;
            }
            int r1 = r0 + 8;
            if (r1 < NN) {
                float2 o = {C[mt][nt][2] + b0, C[mt][nt][3] + b1};
                *reinterpret_cast<float2*>(&O[r1 * HD + c]) = o;
            }
        }
    }
}

// ---------------- per-layer init: agg=0, z=0, m=-inf ------------------------
__global__ void init_layer_kernel() {
    int i = blockIdx.x * blockDim.x + threadIdx.x;
    if (i < NN * HD) g_agg[i] = 0.f;
    if (i < NN * HH) { g_z[i] = 0.f; g_m[i] = -FLT_MAX; }
}

// ---------------- edge logits + segment max (warp per edge) -----------------
__global__ void edge_logits_kernel(const int* __restrict__ src,
                                   const int* __restrict__ dst,
                                   const float* __restrict__ ew,
                                   const float* __restrict__ We) {
    int e = blockIdx.x * 8 + (threadIdx.x >> 5);
    int lane = threadIdx.x & 31;
    if (e >= EE) return;
    int s = src[e], d = dst[e];
    float w = ew[e];
    float acc[HH];
#pragma unroll
    for (int j = 0; j < HH; j++) {
        int dim = lane + 32 * j;
        float ke = g_k[s * HD + dim] + w * We[dim];
        acc[j] = g_q[d * HD + dim] * ke;
    }
#pragma unroll
    for (int o = 16; o; o >>= 1) {
#pragma unroll
        for (int j = 0; j < HH; j++) acc[j] += __shfl_xor_sync(0xffffffffu, acc[j], o);
    }
    const float scale = 0.17677669529663687f;  // 1/sqrt(32)
#pragma unroll
    for (int j = 0; j < HH; j++) {
        if (lane == j) {
            float lg = acc[j] * scale;
            g_p[e * HH + j] = lg;
            atomicMaxF(&g_m[d * HH + j], lg);
        }
    }
}

// ---------------- fused softmax + aggregation (warp per edge) ---------------
// p = exp(logit - m[dst]) computed inline; z accumulated here; division by z
// deferred to ln_res. Aggregates p * (v+e) via float4 REDs.
__global__ void edge_agg_kernel(const int* __restrict__ src,
                                const int* __restrict__ dst,
                                const float* __restrict__ ew,
                                const float* __restrict__ We) {
    int e = blockIdx.x * 8 + (threadIdx.x >> 5);
    int lane = threadIdx.x & 31;
    if (e >= EE) return;
    int s = src[e], d = dst[e];
    float w = ew[e];
    float pv = 0.f;
    if (lane < HH) {
        pv = expf(g_p[e * HH + lane] - g_m[d * HH + lane]);
        atomicAdd(&g_z[d * HH + lane], pv);
    }
    float a0 = __shfl_sync(0xffffffffu, pv, lane >> 3);
    float a1 = __shfl_sync(0xffffffffu, pv, 4 + (lane >> 3));

    int d0 = 4 * lane;  // dims 0..127, head = lane/8
    float4 v4 = *reinterpret_cast<const float4*>(&g_v[s * HD + d0]);
    float4 w4 = *reinterpret_cast<const float4*>(&We[d0]);
    float4 msg;
    msg.x = (v4.x + w * w4.x) * a0;
    msg.y = (v4.y + w * w4.y) * a0;
    msg.z = (v4.z + w * w4.z) * a0;
    msg.w = (v4.w + w * w4.w) * a0;
    redAddV4(&g_agg[d * HD + d0], msg);

    if (lane < 16) {  // dims 128..191, head = 4 + lane/8
        int d1 = 128 + 4 * lane;
        float4 v5 = *reinterpret_cast<const float4*>(&g_v[s * HD + d1]);
        float4 w5 = *reinterpret_cast<const float4*>(&We[d1]);
        float4 m2;
        m2.x = (v5.x + w * w5.x) * a1;
        m2.y = (v5.y + w * w5.y) * a1;
        m2.z = (v5.z + w * w5.z) * a1;
        m2.w = (v5.w + w * w5.w) * a1;
        redAddV4(&g_agg[d * HD + d1], m2);
    }
}

// ---------------- hi = agg/z + skip; h += relu(LN(hi)) (warp per node) ------
__global__ void ln_res_kernel(const float* __restrict__ lg,
                              const float* __restrict__ lb) {
    int n = blockIdx.x * 8 + (threadIdx.x >> 5);
    int lane = threadIdx.x & 31;
    if (n >= NN) return;
    float v[HH];
    float s1 = 0.f;
#pragma unroll
    for (int j = 0; j < HH; j++) {
        int dim = lane + 32 * j;
        float z = g_z[n * HH + j];
        float inv = (z > 0.f) ? (1.0f / z) : 0.f;
        v[j] = g_agg[n * HD + dim] * inv + g_s[n * HD + dim];
        s1 += v[j];
    }
#pragma unroll
    for (int o = 16; o; o >>= 1) s1 += __shfl_xor_sync(0xffffffffu, s1, o);
    float mu = s1 * (1.0f / HD);
    float s2 = 0.f;
#pragma unroll
    for (int j = 0; j < HH; j++) { float dd = v[j] - mu; s2 += dd * dd; }
#pragma unroll
    for (int o = 16; o; o >>= 1) s2 += __shfl_xor_sync(0xffffffffu, s2, o);
    float rstd = rsqrtf(s2 * (1.0f / HD) + 1e-5f);
#pragma unroll
    for (int j = 0; j < HH; j++) {
        int dim = lane + 32 * j;
        float y = (v[j] - mu) * rstd * lg[dim] + lb[dim];
        g_h[n * HD + dim] += fmaxf(y, 0.f);
    }
}

// ---------------- pooling ----------------------------------------------------
__global__ void pool_init_kernel() {
    int i = blockIdx.x * blockDim.x + threadIdx.x;
    if (i < GG * HD) g_pool[i] = 0.f;
    if (i < GG) g_cnt[i] = 0.f;
}

__global__ void pool_kernel(const int* __restrict__ batch) {
    __shared__ float acc[GG * HD];
    __shared__ float scnt[GG];
    int t = threadIdx.x;  // 192
    for (int i = t; i < GG * HD; i += HD) acc[i] = 0.f;
    if (t < GG) scnt[t] = 0.f;
    __syncthreads();
    int per = (NN + gridDim.x - 1) / gridDim.x;
    int n0 = blockIdx.x * per;
    int n1 = min(n0 + per, NN);
    for (int n = n0; n < n1; n++) {
        int g = batch[n];
        acc[g * HD + t] += g_h[n * HD + t];
        if (t == 0) scnt[g] += 1.f;
    }
    __syncthreads();
    for (int i = t; i < GG * HD; i += HD) atomicAdd(&g_pool[i], acc[i]);
    if (t < GG) atomicAdd(&g_cnt[t], scnt[t]);
}

// ---------------- head MLP (block per graph, 192 threads) -------------------
__global__ void head_kernel(const float* __restrict__ ie,
                            const float* __restrict__ fciW, const float* __restrict__ fcib,
                            const float* __restrict__ fcig, const float* __restrict__ fcilb,
                            const float* __restrict__ fc1W, const float* __restrict__ fc1b,
                            const float* __restrict__ fc1g, const float* __restrict__ fc1lb,
                            const float* __restrict__ fc2W, const float* __restrict__ fc2b,
                            const float* __restrict__ fc2g, const float* __restrict__ fc2lb,
                            const float* __restrict__ fc3W, const float* __restrict__ fc3b,
                            float* __restrict__ out) {
    __shared__ float zin[2 * HD];
    __shared__ float buf[HD];
    __shared__ float red[8];
    int t = threadIdx.x;  // 0..191
    int g = blockIdx.x;

    float cnt = fmaxf(g_cnt[g], 1.f);
    zin[t] = g_pool[g * HD + t] / cnt;

    // fc_initial: Linear(1,192) + LN + ReLU
    float iv = ie[g] * fciW[t] + fcib[t];
    float mu = blk_sum(iv, red) * (1.0f / HD);
    float dv = iv - mu;
    float var = blk_sum(dv * dv, red) * (1.0f / HD);
    float rstd = rsqrtf(var + 1e-5f);
    zin[HD + t] = fmaxf(dv * rstd * fcig[t] + fcilb[t], 0.f);
    __syncthreads();

    // fc1: 384 -> 192, LN, ReLU
    float a = fc1b[t];
    for (int k = 0; k < 2 * HD; k++) a += zin[k] * fc1W[k * HD + t];
    mu = blk_sum(a, red) * (1.0f / HD);
    dv = a - mu;
    var = blk_sum(dv * dv, red) * (1.0f / HD);
    rstd = rsqrtf(var + 1e-5f);
    buf[t] = fmaxf(dv * rstd * fc1g[t] + fc1lb[t], 0.f);
    __syncthreads();

    // fc2: 192 -> 96, LN, ReLU
    float a2 = 0.f;
    if (t < 96) {
        a2 = fc2b[t];
        for (int k = 0; k < HD; k++) a2 += buf[k] * fc2W[k * 96 + t];
    }
    mu = blk_sum(t < 96 ? a2 : 0.f, red) * (1.0f / 96.0f);
    dv = a2 - mu;
    var = blk_sum(t < 96 ? dv * dv : 0.f, red) * (1.0f / 96.0f);
    rstd = rsqrtf(var + 1e-5f);
    float r2 = 0.f;
    if (t < 96) r2 = fmaxf(dv * rstd * fc2g[t] + fc2lb[t], 0.f);

    // fc3: 96 -> 1
    float p3 = (t < 96) ? r2 * fc3W[t] : 0.f;
    float tot = blk_sum(p3, red);
    if (t == 0) out[g] = tot + fc3b[0];
}

// ---------------- launch ------------------------------------------------------
extern "C" void kernel_launch(void* const* d_in, const int* in_sizes, int n_in,
                              void* d_out, int out_size) {
    const float* x    = (const float*)d_in[0];
    const int*   ei   = (const int*)d_in[1];
    const float* ew   = (const float*)d_in[2];
    const int*   batch= (const int*)d_in[3];
    const float* ie   = (const float*)d_in[4];
    const float* Wp   = (const float*)d_in[5];
    const float* bp   = (const float*)d_in[6];
    const float* Wq   = (const float*)d_in[7];
    const float* bq   = (const float*)d_in[8];
    const float* Wk   = (const float*)d_in[9];
    const float* bk   = (const float*)d_in[10];
    const float* Wv   = (const float*)d_in[11];
    const float* bv   = (const float*)d_in[12];
    const float* We   = (const float*)d_in[13];
    const float* Ws   = (const float*)d_in[14];
    const float* bs   = (const float*)d_in[15];
    const float* lng  = (const float*)d_in[16];
    const float* lnb  = (const float*)d_in[17];
    const float* fciW = (const float*)d_in[18];
    const float* fcib = (const float*)d_in[19];
    const float* fcig = (const float*)d_in[20];
    const float* fcilb= (const float*)d_in[21];
    const float* fc1W = (const float*)d_in[22];
    const float* fc1b = (const float*)d_in[23];
    const float* fc1g = (const float*)d_in[24];
    const float* fc1lb= (const float*)d_in[25];
    const float* fc2W = (const float*)d_in[26];
    const float* fc2b = (const float*)d_in[27];
    const float* fc2g = (const float*)d_in[28];
    const float* fc2lb= (const float*)d_in[29];
    const float* fc3W = (const float*)d_in[30];
    const float* fc3b = (const float*)d_in[31];
    float* out = (float*)d_out;

    const int* src = ei;
    const int* dst = ei + EE;

    proj_kernel<<<(NN * HD + 255) / 256, 256>>>(x, Wp, bp);
    split_w_kernel<<<864, 256>>>(Wq, Wk, Wv, Ws);   // 12*12*24*2*32 / 256

    for (int i = 0; i < 3; i++) {
        split_h_kernel<<<NTILES * KSTEPS * 4 * 32 / 256, 256>>>();
        gemm_tc_kernel<<<dim3(NTILES / 4, 4), 256>>>(i, bq, bk, bv, bs);
        init_layer_kernel<<<(NN * HD + 255) / 256, 256>>>();
        edge_logits_kernel<<<EE / 8, 256>>>(src, dst, ew, We + i * HD);
        edge_agg_kernel<<<EE / 8, 256>>>(src, dst, ew, We + i * HD);
        ln_res_kernel<<<NN / 8, 256>>>(lng + i * HD, lnb + i * HD);
    }

    pool_init_kernel<<<(GG * HD + 255) / 256, 256>>>();
    pool_kernel<<<512, HD>>>(batch);
    head_kernel<<<GG, HD>>>(ie, fciW, fcib, fcig, fcilb,
                            fc1W, fc1b, fc1g, fc1lb,
                            fc2W, fc2b, fc2g, fc2lb,
                            fc3W, fc3b, out);
}

// round 6
// speedup vs baseline: 2.2140x; 1.2667x over previous
#include <cuda_runtime.h>
#include <cuda_fp16.h>
#include <math.h>
#include <float.h>
#include <stdint.h>

#define NN 100000
#define EE 400000
#define GG 32
#define HH 6
#define HD 192
#define NTILES 6256          // ceil(100000/16)=6250, padded to multiple of 8
#define KSTEPS 12            // 192/16

// ---------------- scratch (device globals; no allocations allowed) ----------
__device__ float g_h[NN * HD];
__device__ float g_q[NN * HD];
__device__ float g_k[NN * HD];
__device__ float g_v[NN * HD];
__device__ float g_s[NN * HD];
__device__ float g_agg[NN * HD];
__device__ float g_m[NN * HH];
__device__ float g_z[NN * HH];
__device__ float g_p[EE * HH];
__device__ float g_pool[GG * HD];
__device__ float g_cnt[GG];

// fp16x2 fragment operands for mma.sync, pre-paired as u64 for LDG.64
// A: index ((tile*KSTEPS+ks)*2+p)*32+lane : lo=reg2p (row r), hi=reg2p+1 (row r+8)
__device__ unsigned long long g_afrag[(size_t)NTILES * KSTEPS * 2 * 32];   // 38.4MB
// B: index ((mat*KSTEPS+ks)*24+nt)*32+lane : lo=b0, hi=b1
__device__ unsigned long long g_wfrag[(size_t)12 * KSTEPS * 24 * 32];      // 0.9MB

// ---------------- helpers ---------------------------------------------------
__device__ __forceinline__ void atomicMaxF(float* addr, float v) {
    if (v >= 0.0f)
        atomicMax((int*)addr, __float_as_int(v));
    else
        atomicMin((unsigned int*)addr, __float_as_uint(v));
}

__device__ __forceinline__ void redAddV4(float* addr, float4 v) {
    asm volatile("red.global.add.v4.f32 [%0], {%1,%2,%3,%4};"
                 :: "l"(addr), "f"(v.x), "f"(v.y), "f"(v.z), "f"(v.w)
                 : "memory");
}

// pack two floats as fp16x2 (a -> low half, b -> high half), rn
__device__ __forceinline__ unsigned fp2(float a, float b) {
    unsigned r;
    asm("cvt.rn.f16x2.f32 %0, %1, %2;" : "=r"(r) : "f"(b), "f"(a));
    return r;
}

__device__ __forceinline__ void mma_fp16(float* c, const unsigned* a, const unsigned* b) {
    asm("mma.sync.aligned.m16n8k16.row.col.f32.f16.f16.f32 "
        "{%0,%1,%2,%3}, {%4,%5,%6,%7}, {%8,%9}, {%0,%1,%2,%3};"
        : "+f"(c[0]), "+f"(c[1]), "+f"(c[2]), "+f"(c[3])
        : "r"(a[0]), "r"(a[1]), "r"(a[2]), "r"(a[3]), "r"(b[0]), "r"(b[1]));
}

// block reduce over 192 threads (6 warps)
__device__ __forceinline__ float blk_sum(float v, float* red) {
    int t = threadIdx.x, lane = t & 31, w = t >> 5;
#pragma unroll
    for (int o = 16; o; o >>= 1) v += __shfl_xor_sync(0xffffffffu, v, o);
    __syncthreads();
    if (lane == 0) red[w] = v;
    __syncthreads();
    float s = 0.f;
#pragma unroll
    for (int i = 0; i < 6; i++) s += red[i];
    return s;
}

// ---------------- input projection: h = x @ Wp + bp -------------------------
__global__ void proj_kernel(const float* __restrict__ x,
                            const float* __restrict__ Wp,
                            const float* __restrict__ bp) {
    int i = blockIdx.x * blockDim.x + threadIdx.x;
    if (i >= NN * HD) return;
    int n = i / HD, d = i - n * HD;
    const float* xr = x + n * 4;
    float acc = bp[d];
    acc += xr[0] * Wp[d] + xr[1] * Wp[HD + d] + xr[2] * Wp[2 * HD + d] + xr[3] * Wp[3 * HD + d];
    g_h[i] = acc;
}

// ---------------- convert h into A-fragment layout (fp16 pairs) -------------
__global__ void split_h_kernel() {
    int t = blockIdx.x * 256 + threadIdx.x;
    int lane = t & 31;
    int p = (t >> 5) & 1;
    int ks = (t >> 6) % KSTEPS;
    int tile = t / (KSTEPS * 2 * 32);
    int row = tile * 16 + (lane >> 2);
    int k = ks * 16 + ((lane & 3) << 1) + (p << 3);
    float x0 = 0.f, x1 = 0.f, x2 = 0.f, x3 = 0.f;
    if (row < NN) {
        const float* q = &g_h[row * HD + k];
        x0 = q[0]; x1 = q[1];
    }
    if (row + 8 < NN) {
        const float* q = &g_h[(row + 8) * HD + k];
        x2 = q[0]; x3 = q[1];
    }
    unsigned lo = fp2(x0, x1);
    unsigned hi = fp2(x2, x3);
    g_afrag[t] = ((unsigned long long)hi << 32) | lo;
}

// ---------------- convert all 12 weight matrices into B-fragment layout -----
__global__ void split_w_kernel(const float* __restrict__ Wq, const float* __restrict__ Wk,
                               const float* __restrict__ Wv, const float* __restrict__ Ws) {
    int t = blockIdx.x * 256 + threadIdx.x;
    if (t >= 12 * KSTEPS * 24 * 32) return;
    int lane = t & 31;
    int nt = (t >> 5) % 24;
    int ks = ((t >> 5) / 24) % KSTEPS;
    int mat = t / (32 * 24 * KSTEPS);
    int n = nt * 8 + (lane >> 2);
    int k = ks * 16 + ((lane & 3) << 1);
    int which = mat & 3, layer = mat >> 2;
    const float* W = (which == 0 ? Wq : which == 1 ? Wk : which == 2 ? Wv : Ws)
                     + (size_t)layer * HD * HD;
    unsigned lo = fp2(W[k * HD + n], W[(k + 1) * HD + n]);
    unsigned hi = fp2(W[(k + 8) * HD + n], W[(k + 9) * HD + n]);
    g_wfrag[t] = ((unsigned long long)hi << 32) | lo;
}

// ---------------- tensor-core GEMM: O = h @ W + b (single-pass fp16) --------
// CTA: 256 thr = 8 warps, 3 CTAs/SM. warp (wm 0..1, wn 0..3): m32 x n48 tile.
// CTA tile: m64 x n192. grid = (NTILES/4, 4 matrices).
__global__ __launch_bounds__(256, 3) void gemm_tc_kernel(
    int layer,
    const float* __restrict__ bq, const float* __restrict__ bk,
    const float* __restrict__ bv, const float* __restrict__ bs) {
    int w = threadIdx.x >> 5, lane = threadIdx.x & 31;
    int wm = w & 1, wn = w >> 1;
    int tile0 = blockIdx.x * 4 + wm * 2;
    int mat = layer * 4 + blockIdx.y;

    float C[2][6][4];
#pragma unroll
    for (int mt = 0; mt < 2; mt++)
#pragma unroll
        for (int nt = 0; nt < 6; nt++)
#pragma unroll
            for (int i = 0; i < 4; i++) C[mt][nt][i] = 0.f;

    const unsigned long long* __restrict__ A = g_afrag;
    const unsigned long long* __restrict__ B =
        g_wfrag + (size_t)mat * KSTEPS * 24 * 32;

#pragma unroll 3
    for (int ks = 0; ks < KSTEPS; ks++) {
        unsigned a[2][4];
#pragma unroll
        for (int mt = 0; mt < 2; mt++) {
            size_t base = (((size_t)(tile0 + mt) * KSTEPS + ks) * 2) * 32 + lane;
            unsigned long long v0 = __ldg(&A[base]);
            unsigned long long v1 = __ldg(&A[base + 32]);
            a[mt][0] = (unsigned)v0; a[mt][1] = (unsigned)(v0 >> 32);
            a[mt][2] = (unsigned)v1; a[mt][3] = (unsigned)(v1 >> 32);
        }
#pragma unroll
        for (int nt = 0; nt < 6; nt++) {
            int ntg = wn * 6 + nt;
            unsigned long long bv = __ldg(&B[((size_t)ks * 24 + ntg) * 32 + lane]);
            unsigned b[2] = {(unsigned)bv, (unsigned)(bv >> 32)};
#pragma unroll
            for (int mt = 0; mt < 2; mt++) mma_fp16(C[mt][nt], a[mt], b);
        }
    }

    float* O = (blockIdx.y == 0) ? g_q : (blockIdx.y == 1) ? g_k
             : (blockIdx.y == 2) ? g_v : g_s;
    const float* Bv = ((blockIdx.y == 0) ? bq : (blockIdx.y == 1) ? bk
                     : (blockIdx.y == 2) ? bv : bs) + layer * HD;
#pragma unroll
    for (int mt = 0; mt < 2; mt++) {
        int r0 = (tile0 + mt) * 16 + (lane >> 2);
#pragma unroll
        for (int nt = 0; nt < 6; nt++) {
            int c = (wn * 6 + nt) * 8 + (lane & 3) * 2;
            float b0 = Bv[c], b1 = Bv[c + 1];
            if (r0 < NN) {
                float2 o = {C[mt][nt][0] + b0, C[mt][nt][1] + b1};
                *reinterpret_cast<float2*>(&O[r0 * HD + c]) = o;
            }
            int r1 = r0 + 8;
            if (r1 < NN) {
                float2 o = {C[mt][nt][2] + b0, C[mt][nt][3] + b1};
                *reinterpret_cast<float2*>(&O[r1 * HD + c]) = o;
            }
        }
    }
}

// ---------------- per-layer init: agg=0, z=0, m=-inf ------------------------
__global__ void init_layer_kernel() {
    int i = blockIdx.x * blockDim.x + threadIdx.x;
    if (i < NN * HD) g_agg[i] = 0.f;
    if (i < NN * HH) { g_z[i] = 0.f; g_m[i] = -FLT_MAX; }
}

// ---------------- edge logits + segment max (warp per edge) -----------------
__global__ void edge_logits_kernel(const int* __restrict__ src,
                                   const int* __restrict__ dst,
                                   const float* __restrict__ ew,
                                   const float* __restrict__ We) {
    int e = blockIdx.x * 8 + (threadIdx.x >> 5);
    int lane = threadIdx.x & 31;
    if (e >= EE) return;
    int s = src[e], d = dst[e];
    float w = ew[e];
    float acc[HH];
#pragma unroll
    for (int j = 0; j < HH; j++) {
        int dim = lane + 32 * j;
        float ke = g_k[s * HD + dim] + w * We[dim];
        acc[j] = g_q[d * HD + dim] * ke;
    }
#pragma unroll
    for (int o = 16; o; o >>= 1) {
#pragma unroll
        for (int j = 0; j < HH; j++) acc[j] += __shfl_xor_sync(0xffffffffu, acc[j], o);
    }
    const float scale = 0.17677669529663687f;  // 1/sqrt(32)
#pragma unroll
    for (int j = 0; j < HH; j++) {
        if (lane == j) {
            float lg = acc[j] * scale;
            g_p[e * HH + j] = lg;
            atomicMaxF(&g_m[d * HH + j], lg);
        }
    }
}

// ---------------- fused softmax + aggregation (warp per edge) ---------------
__global__ void edge_agg_kernel(const int* __restrict__ src,
                                const int* __restrict__ dst,
                                const float* __restrict__ ew,
                                const float* __restrict__ We) {
    int e = blockIdx.x * 8 + (threadIdx.x >> 5);
    int lane = threadIdx.x & 31;
    if (e >= EE) return;
    int s = src[e], d = dst[e];
    float w = ew[e];
    float pv = 0.f;
    if (lane < HH) {
        pv = expf(g_p[e * HH + lane] - g_m[d * HH + lane]);
        atomicAdd(&g_z[d * HH + lane], pv);
    }
    float a0 = __shfl_sync(0xffffffffu, pv, lane >> 3);
    float a1 = __shfl_sync(0xffffffffu, pv, 4 + (lane >> 3));

    int d0 = 4 * lane;  // dims 0..127, head = lane/8
    float4 v4 = *reinterpret_cast<const float4*>(&g_v[s * HD + d0]);
    float4 w4 = *reinterpret_cast<const float4*>(&We[d0]);
    float4 msg;
    msg.x = (v4.x + w * w4.x) * a0;
    msg.y = (v4.y + w * w4.y) * a0;
    msg.z = (v4.z + w * w4.z) * a0;
    msg.w = (v4.w + w * w4.w) * a0;
    redAddV4(&g_agg[d * HD + d0], msg);

    if (lane < 16) {  // dims 128..191, head = 4 + lane/8
        int d1 = 128 + 4 * lane;
        float4 v5 = *reinterpret_cast<const float4*>(&g_v[s * HD + d1]);
        float4 w5 = *reinterpret_cast<const float4*>(&We[d1]);
        float4 m2;
        m2.x = (v5.x + w * w5.x) * a1;
        m2.y = (v5.y + w * w5.y) * a1;
        m2.z = (v5.z + w * w5.z) * a1;
        m2.w = (v5.w + w * w5.w) * a1;
        redAddV4(&g_agg[d * HD + d1], m2);
    }
}

// ---------------- hi = agg/z + skip; h += relu(LN(hi)) (warp per node) ------
__global__ void ln_res_kernel(const float* __restrict__ lg,
                              const float* __restrict__ lb) {
    int n = blockIdx.x * 8 + (threadIdx.x >> 5);
    int lane = threadIdx.x & 31;
    if (n >= NN) return;
    float v[HH];
    float s1 = 0.f;
#pragma unroll
    for (int j = 0; j < HH; j++) {
        int dim = lane + 32 * j;
        float z = g_z[n * HH + j];
        float inv = (z > 0.f) ? (1.0f / z) : 0.f;
        v[j] = g_agg[n * HD + dim] * inv + g_s[n * HD + dim];
        s1 += v[j];
    }
#pragma unroll
    for (int o = 16; o; o >>= 1) s1 += __shfl_xor_sync(0xffffffffu, s1, o);
    float mu = s1 * (1.0f / HD);
    float s2 = 0.f;
#pragma unroll
    for (int j = 0; j < HH; j++) { float dd = v[j] - mu; s2 += dd * dd; }
#pragma unroll
    for (int o = 16; o; o >>= 1) s2 += __shfl_xor_sync(0xffffffffu, s2, o);
    float rstd = rsqrtf(s2 * (1.0f / HD) + 1e-5f);
#pragma unroll
    for (int j = 0; j < HH; j++) {
        int dim = lane + 32 * j;
        float y = (v[j] - mu) * rstd * lg[dim] + lb[dim];
        g_h[n * HD + dim] += fmaxf(y, 0.f);
    }
}

// ---------------- pooling ----------------------------------------------------
__global__ void pool_init_kernel() {
    int i = blockIdx.x * blockDim.x + threadIdx.x;
    if (i < GG * HD) g_pool[i] = 0.f;
    if (i < GG) g_cnt[i] = 0.f;
}

__global__ void pool_kernel(const int* __restrict__ batch) {
    __shared__ float acc[GG * HD];
    __shared__ float scnt[GG];
    int t = threadIdx.x;  // 192
    for (int i = t; i < GG * HD; i += HD) acc[i] = 0.f;
    if (t < GG) scnt[t] = 0.f;
    __syncthreads();
    int per = (NN + gridDim.x - 1) / gridDim.x;
    int n0 = blockIdx.x * per;
    int n1 = min(n0 + per, NN);
    for (int n = n0; n < n1; n++) {
        int g = batch[n];
        acc[g * HD + t] += g_h[n * HD + t];
        if (t == 0) scnt[g] += 1.f;
    }
    __syncthreads();
    for (int i = t; i < GG * HD; i += HD) atomicAdd(&g_pool[i], acc[i]);
    if (t < GG) atomicAdd(&g_cnt[t], scnt[t]);
}

// ---------------- head MLP (block per graph, 192 threads) -------------------
__global__ void head_kernel(const float* __restrict__ ie,
                            const float* __restrict__ fciW, const float* __restrict__ fcib,
                            const float* __restrict__ fcig, const float* __restrict__ fcilb,
                            const float* __restrict__ fc1W, const float* __restrict__ fc1b,
                            const float* __restrict__ fc1g, const float* __restrict__ fc1lb,
                            const float* __restrict__ fc2W, const float* __restrict__ fc2b,
                            const float* __restrict__ fc2g, const float* __restrict__ fc2lb,
                            const float* __restrict__ fc3W, const float* __restrict__ fc3b,
                            float* __restrict__ out) {
    __shared__ float zin[2 * HD];
    __shared__ float buf[HD];
    __shared__ float red[8];
    int t = threadIdx.x;  // 0..191
    int g = blockIdx.x;

    float cnt = fmaxf(g_cnt[g], 1.f);
    zin[t] = g_pool[g * HD + t] / cnt;

    // fc_initial: Linear(1,192) + LN + ReLU
    float iv = ie[g] * fciW[t] + fcib[t];
    float mu = blk_sum(iv, red) * (1.0f / HD);
    float dv = iv - mu;
    float var = blk_sum(dv * dv, red) * (1.0f / HD);
    float rstd = rsqrtf(var + 1e-5f);
    zin[HD + t] = fmaxf(dv * rstd * fcig[t] + fcilb[t], 0.f);
    __syncthreads();

    // fc1: 384 -> 192, LN, ReLU
    float a = fc1b[t];
    for (int k = 0; k < 2 * HD; k++) a += zin[k] * fc1W[k * HD + t];
    mu = blk_sum(a, red) * (1.0f / HD);
    dv = a - mu;
    var = blk_sum(dv * dv, red) * (1.0f / HD);
    rstd = rsqrtf(var + 1e-5f);
    buf[t] = fmaxf(dv * rstd * fc1g[t] + fc1lb[t], 0.f);
    __syncthreads();

    // fc2: 192 -> 96, LN, ReLU
    float a2 = 0.f;
    if (t < 96) {
        a2 = fc2b[t];
        for (int k = 0; k < HD; k++) a2 += buf[k] * fc2W[k * 96 + t];
    }
    mu = blk_sum(t < 96 ? a2 : 0.f, red) * (1.0f / 96.0f);
    dv = a2 - mu;
    var = blk_sum(t < 96 ? dv * dv : 0.f, red) * (1.0f / 96.0f);
    rstd = rsqrtf(var + 1e-5f);
    float r2 = 0.f;
    if (t < 96) r2 = fmaxf(dv * rstd * fc2g[t] + fc2lb[t], 0.f);

    // fc3: 96 -> 1
    float p3 = (t < 96) ? r2 * fc3W[t] : 0.f;
    float tot = blk_sum(p3, red);
    if (t == 0) out[g] = tot + fc3b[0];
}

// ---------------- launch ------------------------------------------------------
extern "C" void kernel_launch(void* const* d_in, const int* in_sizes, int n_in,
                              void* d_out, int out_size) {
    const float* x    = (const float*)d_in[0];
    const int*   ei   = (const int*)d_in[1];
    const float* ew   = (const float*)d_in[2];
    const int*   batch= (const int*)d_in[3];
    const float* ie   = (const float*)d_in[4];
    const float* Wp   = (const float*)d_in[5];
    const float* bp   = (const float*)d_in[6];
    const float* Wq   = (const float*)d_in[7];
    const float* bq   = (const float*)d_in[8];
    const float* Wk   = (const float*)d_in[9];
    const float* bk   = (const float*)d_in[10];
    const float* Wv   = (const float*)d_in[11];
    const float* bv   = (const float*)d_in[12];
    const float* We   = (const float*)d_in[13];
    const float* Ws   = (const float*)d_in[14];
    const float* bs   = (const float*)d_in[15];
    const float* lng  = (const float*)d_in[16];
    const float* lnb  = (const float*)d_in[17];
    const float* fciW = (const float*)d_in[18];
    const float* fcib = (const float*)d_in[19];
    const float* fcig = (const float*)d_in[20];
    const float* fcilb= (const float*)d_in[21];
    const float* fc1W = (const float*)d_in[22];
    const float* fc1b = (const float*)d_in[23];
    const float* fc1g = (const float*)d_in[24];
    const float* fc1lb= (const float*)d_in[25];
    const float* fc2W = (const float*)d_in[26];
    const float* fc2b = (const float*)d_in[27];
    const float* fc2g = (const float*)d_in[28];
    const float* fc2lb= (const float*)d_in[29];
    const float* fc3W = (const float*)d_in[30];
    const float* fc3b = (const float*)d_in[31];
    float* out = (float*)d_out;

    const int* src = ei;
    const int* dst = ei + EE;

    proj_kernel<<<(NN * HD + 255) / 256, 256>>>(x, Wp, bp);
    split_w_kernel<<<(12 * KSTEPS * 24 * 32 + 255) / 256, 256>>>(Wq, Wk, Wv, Ws);

    for (int i = 0; i < 3; i++) {
        split_h_kernel<<<NTILES * KSTEPS * 2 * 32 / 256, 256>>>();
        gemm_tc_kernel<<<dim3(NTILES / 4, 4), 256>>>(i, bq, bk, bv, bs);
        init_layer_kernel<<<(NN * HD + 255) / 256, 256>>>();
        edge_logits_kernel<<<EE / 8, 256>>>(src, dst, ew, We + i * HD);
        edge_agg_kernel<<<EE / 8, 256>>>(src, dst, ew, We + i * HD);
        ln_res_kernel<<<NN / 8, 256>>>(lng + i * HD, lnb + i * HD);
    }

    pool_init_kernel<<<(GG * HD + 255) / 256, 256>>>();
    pool_kernel<<<512, HD>>>(batch);
    head_kernel<<<GG, HD>>>(ie, fciW, fcib, fcig, fcilb,
                            fc1W, fc1b, fc1g, fc1lb,
                            fc2W, fc2b, fc2g, fc2lb,
                            fc3W, fc3b, out);
}

// round 7
// speedup vs baseline: 2.7414x; 1.2382x over previous
#include <cuda_runtime.h>
#include <cuda_fp16.h>
#include <math.h>
#include <float.h>
#include <stdint.h>

#define NN 100000
#define EE 400000
#define GG 32
#define HH 6
#define HD 192
#define NTILES 6256          // ceil(100000/16)=6250, padded to multiple of 8
#define KSTEPS 12            // 192/16

// ---------------- scratch (device globals; no allocations allowed) ----------
__device__ float g_h[NN * HD];
__device__ __half g_qh[NN * HD];
__device__ __half g_kh[NN * HD];
__device__ __half g_vh[NN * HD];
__device__ float g_s[NN * HD];
__device__ float g_agg[NN * HD];
__device__ float g_m[NN * HH];
__device__ float g_z[NN * HH];
__device__ float g_p[EE * HH];
__device__ float g_pool[GG * HD];
__device__ float g_cnt[GG];

// fp16x2 fragment operands for mma.sync, pre-paired as u64 for LDG.64
__device__ unsigned long long g_afrag[(size_t)NTILES * KSTEPS * 2 * 32];   // 38.4MB
__device__ unsigned long long g_wfrag[(size_t)12 * KSTEPS * 24 * 32];      // 0.9MB

// ---------------- helpers ---------------------------------------------------
__device__ __forceinline__ void atomicMaxF(float* addr, float v) {
    if (v >= 0.0f)
        atomicMax((int*)addr, __float_as_int(v));
    else
        atomicMin((unsigned int*)addr, __float_as_uint(v));
}

__device__ __forceinline__ void redAddV4(float* addr, float4 v) {
    asm volatile("red.global.add.v4.f32 [%0], {%1,%2,%3,%4};"
                 :: "l"(addr), "f"(v.x), "f"(v.y), "f"(v.z), "f"(v.w)
                 : "memory");
}

// pack two floats as fp16x2 (a -> low half, b -> high half), rn
__device__ __forceinline__ unsigned fp2(float a, float b) {
    unsigned r;
    asm("cvt.rn.f16x2.f32 %0, %1, %2;" : "=r"(r) : "f"(b), "f"(a));
    return r;
}

__device__ __forceinline__ void mma_fp16(float* c, const unsigned* a, const unsigned* b) {
    asm("mma.sync.aligned.m16n8k16.row.col.f32.f16.f16.f32 "
        "{%0,%1,%2,%3}, {%4,%5,%6,%7}, {%8,%9}, {%0,%1,%2,%3};"
        : "+f"(c[0]), "+f"(c[1]), "+f"(c[2]), "+f"(c[3])
        : "r"(a[0]), "r"(a[1]), "r"(a[2]), "r"(a[3]), "r"(b[0]), "r"(b[1]));
}

// block reduce over 192 threads (6 warps)
__device__ __forceinline__ float blk_sum(float v, float* red) {
    int t = threadIdx.x, lane = t & 31, w = t >> 5;
#pragma unroll
    for (int o = 16; o; o >>= 1) v += __shfl_xor_sync(0xffffffffu, v, o);
    __syncthreads();
    if (lane == 0) red[w] = v;
    __syncthreads();
    float s = 0.f;
#pragma unroll
    for (int i = 0; i < 6; i++) s += red[i];
    return s;
}

// ---------------- input projection: h = x @ Wp + bp -------------------------
__global__ void proj_kernel(const float* __restrict__ x,
                            const float* __restrict__ Wp,
                            const float* __restrict__ bp) {
    int i = blockIdx.x * blockDim.x + threadIdx.x;
    if (i >= NN * HD) return;
    int n = i / HD, d = i - n * HD;
    const float* xr = x + n * 4;
    float acc = bp[d];
    acc += xr[0] * Wp[d] + xr[1] * Wp[HD + d] + xr[2] * Wp[2 * HD + d] + xr[3] * Wp[3 * HD + d];
    g_h[i] = acc;
}

// ---------------- convert h into A-fragment layout (fp16 pairs) -------------
__global__ void split_h_kernel() {
    int t = blockIdx.x * 256 + threadIdx.x;
    int lane = t & 31;
    int p = (t >> 5) & 1;
    int ks = (t >> 6) % KSTEPS;
    int tile = t / (KSTEPS * 2 * 32);
    int row = tile * 16 + (lane >> 2);
    int k = ks * 16 + ((lane & 3) << 1) + (p << 3);
    float x0 = 0.f, x1 = 0.f, x2 = 0.f, x3 = 0.f;
    if (row < NN) {
        const float* q = &g_h[row * HD + k];
        x0 = q[0]; x1 = q[1];
    }
    if (row + 8 < NN) {
        const float* q = &g_h[(row + 8) * HD + k];
        x2 = q[0]; x3 = q[1];
    }
    unsigned lo = fp2(x0, x1);
    unsigned hi = fp2(x2, x3);
    g_afrag[t] = ((unsigned long long)hi << 32) | lo;
}

// ---------------- convert all 12 weight matrices into B-fragment layout -----
__global__ void split_w_kernel(const float* __restrict__ Wq, const float* __restrict__ Wk,
                               const float* __restrict__ Wv, const float* __restrict__ Ws) {
    int t = blockIdx.x * 256 + threadIdx.x;
    if (t >= 12 * KSTEPS * 24 * 32) return;
    int lane = t & 31;
    int nt = (t >> 5) % 24;
    int ks = ((t >> 5) / 24) % KSTEPS;
    int mat = t / (32 * 24 * KSTEPS);
    int n = nt * 8 + (lane >> 2);
    int k = ks * 16 + ((lane & 3) << 1);
    int which = mat & 3, layer = mat >> 2;
    const float* W = (which == 0 ? Wq : which == 1 ? Wk : which == 2 ? Wv : Ws)
                     + (size_t)layer * HD * HD;
    unsigned lo = fp2(W[k * HD + n], W[(k + 1) * HD + n]);
    unsigned hi = fp2(W[(k + 8) * HD + n], W[(k + 9) * HD + n]);
    g_wfrag[t] = ((unsigned long long)hi << 32) | lo;
}

// ---------------- tensor-core GEMM: O = h @ W + b (single-pass fp16) --------
// CTA: 256 thr = 8 warps, 3 CTAs/SM. warp (wm 0..1, wn 0..3): m32 x n48 tile.
// q,k,v outputs stored fp16; skip output stored fp32.
__global__ __launch_bounds__(256, 3) void gemm_tc_kernel(
    int layer,
    const float* __restrict__ bq, const float* __restrict__ bk,
    const float* __restrict__ bv, const float* __restrict__ bs) {
    int w = threadIdx.x >> 5, lane = threadIdx.x & 31;
    int wm = w & 1, wn = w >> 1;
    int tile0 = blockIdx.x * 4 + wm * 2;
    int mat = layer * 4 + blockIdx.y;

    float C[2][6][4];
#pragma unroll
    for (int mt = 0; mt < 2; mt++)
#pragma unroll
        for (int nt = 0; nt < 6; nt++)
#pragma unroll
            for (int i = 0; i < 4; i++) C[mt][nt][i] = 0.f;

    const unsigned long long* __restrict__ A = g_afrag;
    const unsigned long long* __restrict__ B =
        g_wfrag + (size_t)mat * KSTEPS * 24 * 32;

#pragma unroll 3
    for (int ks = 0; ks < KSTEPS; ks++) {
        unsigned a[2][4];
#pragma unroll
        for (int mt = 0; mt < 2; mt++) {
            size_t base = (((size_t)(tile0 + mt) * KSTEPS + ks) * 2) * 32 + lane;
            unsigned long long v0 = __ldg(&A[base]);
            unsigned long long v1 = __ldg(&A[base + 32]);
            a[mt][0] = (unsigned)v0; a[mt][1] = (unsigned)(v0 >> 32);
            a[mt][2] = (unsigned)v1; a[mt][3] = (unsigned)(v1 >> 32);
        }
#pragma unroll
        for (int nt = 0; nt < 6; nt++) {
            int ntg = wn * 6 + nt;
            unsigned long long bv = __ldg(&B[((size_t)ks * 24 + ntg) * 32 + lane]);
            unsigned b[2] = {(unsigned)bv, (unsigned)(bv >> 32)};
#pragma unroll
            for (int mt = 0; mt < 2; mt++) mma_fp16(C[mt][nt], a[mt], b);
        }
    }

    const float* Bv = ((blockIdx.y == 0) ? bq : (blockIdx.y == 1) ? bk
                     : (blockIdx.y == 2) ? bv : bs) + layer * HD;
    if (blockIdx.y < 3) {
        __half* O = (blockIdx.y == 0) ? g_qh : (blockIdx.y == 1) ? g_kh : g_vh;
#pragma unroll
        for (int mt = 0; mt < 2; mt++) {
            int r0 = (tile0 + mt) * 16 + (lane >> 2);
#pragma unroll
            for (int nt = 0; nt < 6; nt++) {
                int c = (wn * 6 + nt) * 8 + (lane & 3) * 2;
                float b0 = Bv[c], b1 = Bv[c + 1];
                if (r0 < NN)
                    *reinterpret_cast<__half2*>(&O[r0 * HD + c]) =
                        __floats2half2_rn(C[mt][nt][0] + b0, C[mt][nt][1] + b1);
                int r1 = r0 + 8;
                if (r1 < NN)
                    *reinterpret_cast<__half2*>(&O[r1 * HD + c]) =
                        __floats2half2_rn(C[mt][nt][2] + b0, C[mt][nt][3] + b1);
            }
        }
    } else {
#pragma unroll
        for (int mt = 0; mt < 2; mt++) {
            int r0 = (tile0 + mt) * 16 + (lane >> 2);
#pragma unroll
            for (int nt = 0; nt < 6; nt++) {
                int c = (wn * 6 + nt) * 8 + (lane & 3) * 2;
                float b0 = Bv[c], b1 = Bv[c + 1];
                if (r0 < NN) {
                    float2 o = {C[mt][nt][0] + b0, C[mt][nt][1] + b1};
                    *reinterpret_cast<float2*>(&g_s[r0 * HD + c]) = o;
                }
                int r1 = r0 + 8;
                if (r1 < NN) {
                    float2 o = {C[mt][nt][2] + b0, C[mt][nt][3] + b1};
                    *reinterpret_cast<float2*>(&g_s[r1 * HD + c]) = o;
                }
            }
        }
    }
}

// ---------------- per-layer init: agg=0, z=0, m=-inf ------------------------
__global__ void init_layer_kernel() {
    int i = blockIdx.x * blockDim.x + threadIdx.x;
    if (i < NN * HD) g_agg[i] = 0.f;
    if (i < NN * HH) { g_z[i] = 0.f; g_m[i] = -FLT_MAX; }
}

// ---------------- edge logits + segment max (warp per edge, fp16 gathers) ---
// lane owns dim pair (64j + 2*lane); head = 2j + (lane>=16).
__global__ void edge_logits_kernel(const int* __restrict__ src,
                                   const int* __restrict__ dst,
                                   const float* __restrict__ ew,
                                   const float* __restrict__ We) {
    int e = blockIdx.x * 8 + (threadIdx.x >> 5);
    int lane = threadIdx.x & 31;
    if (e >= EE) return;
    int s = src[e], d = dst[e];
    float w = ew[e];
    const __half2* Q2 = (const __half2*)g_qh + (size_t)d * 96;
    const __half2* K2 = (const __half2*)g_kh + (size_t)s * 96;
    const float2* We2 = (const float2*)We;
    float acc[3];
#pragma unroll
    for (int j = 0; j < 3; j++) {
        int idx = 32 * j + lane;
        float2 q = __half22float2(Q2[idx]);
        float2 k = __half22float2(K2[idx]);
        float2 e2 = We2[idx];
        acc[j] = q.x * (k.x + w * e2.x) + q.y * (k.y + w * e2.y);
    }
#pragma unroll
    for (int o = 8; o; o >>= 1) {
#pragma unroll
        for (int j = 0; j < 3; j++) acc[j] += __shfl_xor_sync(0xffffffffu, acc[j], o);
    }
    const float scale = 0.17677669529663687f;  // 1/sqrt(32)
    if ((lane & 15) == 0) {
        int hb = lane >> 4;
#pragma unroll
        for (int j = 0; j < 3; j++) {
            int hh = 2 * j + hb;
            float lg = acc[j] * scale;
            g_p[e * HH + hh] = lg;
            atomicMaxF(&g_m[d * HH + hh], lg);
        }
    }
}

// ---------------- fused softmax + aggregation (warp per edge, fp16 v) -------
__global__ void edge_agg_kernel(const int* __restrict__ src,
                                const int* __restrict__ dst,
                                const float* __restrict__ ew,
                                const float* __restrict__ We) {
    int e = blockIdx.x * 8 + (threadIdx.x >> 5);
    int lane = threadIdx.x & 31;
    if (e >= EE) return;
    int s = src[e], d = dst[e];
    float w = ew[e];
    float pv = 0.f;
    if (lane < HH) {
        pv = expf(g_p[e * HH + lane] - g_m[d * HH + lane]);
        atomicAdd(&g_z[d * HH + lane], pv);
    }
    float a0 = __shfl_sync(0xffffffffu, pv, lane >> 3);
    float a1 = __shfl_sync(0xffffffffu, pv, 4 + (lane >> 3));

    const __half2* V2 = (const __half2*)g_vh + (size_t)s * 96;

    int d0 = 4 * lane;  // dims 0..127, head = lane/8
    uint2 vv = *reinterpret_cast<const uint2*>(V2 + 2 * lane);
    float2 vl = __half22float2(*reinterpret_cast<__half2*>(&vv.x));
    float2 vh = __half22float2(*reinterpret_cast<__half2*>(&vv.y));
    float4 w4 = *reinterpret_cast<const float4*>(&We[d0]);
    float4 msg;
    msg.x = (vl.x + w * w4.x) * a0;
    msg.y = (vl.y + w * w4.y) * a0;
    msg.z = (vh.x + w * w4.z) * a0;
    msg.w = (vh.y + w * w4.w) * a0;
    redAddV4(&g_agg[d * HD + d0], msg);

    if (lane < 16) {  // dims 128..191, head = 4 + lane/8
        int d1 = 128 + 4 * lane;
        uint2 v2 = *reinterpret_cast<const uint2*>(V2 + 64 + 2 * lane);
        float2 xl = __half22float2(*reinterpret_cast<__half2*>(&v2.x));
        float2 xh = __half22float2(*reinterpret_cast<__half2*>(&v2.y));
        float4 w5 = *reinterpret_cast<const float4*>(&We[d1]);
        float4 m2;
        m2.x = (xl.x + w * w5.x) * a1;
        m2.y = (xl.y + w * w5.y) * a1;
        m2.z = (xh.x + w * w5.z) * a1;
        m2.w = (xh.y + w * w5.w) * a1;
        redAddV4(&g_agg[d * HD + d1], m2);
    }
}

// ---------------- hi = agg/z + skip; h += relu(LN(hi)) (warp per node) ------
__global__ void ln_res_kernel(const float* __restrict__ lg,
                              const float* __restrict__ lb) {
    int n = blockIdx.x * 8 + (threadIdx.x >> 5);
    int lane = threadIdx.x & 31;
    if (n >= NN) return;
    float v[HH];
    float s1 = 0.f;
#pragma unroll
    for (int j = 0; j < HH; j++) {
        int dim = lane + 32 * j;
        float z = g_z[n * HH + j];
        float inv = (z > 0.f) ? (1.0f / z) : 0.f;
        v[j] = g_agg[n * HD + dim] * inv + g_s[n * HD + dim];
        s1 += v[j];
    }
#pragma unroll
    for (int o = 16; o; o >>= 1) s1 += __shfl_xor_sync(0xffffffffu, s1, o);
    float mu = s1 * (1.0f / HD);
    float s2 = 0.f;
#pragma unroll
    for (int j = 0; j < HH; j++) { float dd = v[j] - mu; s2 += dd * dd; }
#pragma unroll
    for (int o = 16; o; o >>= 1) s2 += __shfl_xor_sync(0xffffffffu, s2, o);
    float rstd = rsqrtf(s2 * (1.0f / HD) + 1e-5f);
#pragma unroll
    for (int j = 0; j < HH; j++) {
        int dim = lane + 32 * j;
        float y = (v[j] - mu) * rstd * lg[dim] + lb[dim];
        g_h[n * HD + dim] += fmaxf(y, 0.f);
    }
}

// ---------------- pooling ----------------------------------------------------
__global__ void pool_init_kernel() {
    int i = blockIdx.x * blockDim.x + threadIdx.x;
    if (i < GG * HD) g_pool[i] = 0.f;
    if (i < GG) g_cnt[i] = 0.f;
}

__global__ void pool_kernel(const int* __restrict__ batch) {
    __shared__ float acc[GG * HD];
    __shared__ float scnt[GG];
    int t = threadIdx.x;  // 192
    for (int i = t; i < GG * HD; i += HD) acc[i] = 0.f;
    if (t < GG) scnt[t] = 0.f;
    __syncthreads();
    int per = (NN + gridDim.x - 1) / gridDim.x;
    int n0 = blockIdx.x * per;
    int n1 = min(n0 + per, NN);
    for (int n = n0; n < n1; n++) {
        int g = batch[n];
        acc[g * HD + t] += g_h[n * HD + t];
        if (t == 0) scnt[g] += 1.f;
    }
    __syncthreads();
    for (int i = t; i < GG * HD; i += HD) atomicAdd(&g_pool[i], acc[i]);
    if (t < GG) atomicAdd(&g_cnt[t], scnt[t]);
}

// ---------------- head MLP (block per graph, 192 threads) -------------------
__global__ void head_kernel(const float* __restrict__ ie,
                            const float* __restrict__ fciW, const float* __restrict__ fcib,
                            const float* __restrict__ fcig, const float* __restrict__ fcilb,
                            const float* __restrict__ fc1W, const float* __restrict__ fc1b,
                            const float* __restrict__ fc1g, const float* __restrict__ fc1lb,
                            const float* __restrict__ fc2W, const float* __restrict__ fc2b,
                            const float* __restrict__ fc2g, const float* __restrict__ fc2lb,
                            const float* __restrict__ fc3W, const float* __restrict__ fc3b,
                            float* __restrict__ out) {
    __shared__ float zin[2 * HD];
    __shared__ float buf[HD];
    __shared__ float red[8];
    int t = threadIdx.x;  // 0..191
    int g = blockIdx.x;

    float cnt = fmaxf(g_cnt[g], 1.f);
    zin[t] = g_pool[g * HD + t] / cnt;

    // fc_initial: Linear(1,192) + LN + ReLU
    float iv = ie[g] * fciW[t] + fcib[t];
    float mu = blk_sum(iv, red) * (1.0f / HD);
    float dv = iv - mu;
    float var = blk_sum(dv * dv, red) * (1.0f / HD);
    float rstd = rsqrtf(var + 1e-5f);
    zin[HD + t] = fmaxf(dv * rstd * fcig[t] + fcilb[t], 0.f);
    __syncthreads();

    // fc1: 384 -> 192, LN, ReLU
    float a = fc1b[t];
    for (int k = 0; k < 2 * HD; k++) a += zin[k] * fc1W[k * HD + t];
    mu = blk_sum(a, red) * (1.0f / HD);
    dv = a - mu;
    var = blk_sum(dv * dv, red) * (1.0f / HD);
    rstd = rsqrtf(var + 1e-5f);
    buf[t] = fmaxf(dv * rstd * fc1g[t] + fc1lb[t], 0.f);
    __syncthreads();

    // fc2: 192 -> 96, LN, ReLU
    float a2 = 0.f;
    if (t < 96) {
        a2 = fc2b[t];
        for (int k = 0; k < HD; k++) a2 += buf[k] * fc2W[k * 96 + t];
    }
    mu = blk_sum(t < 96 ? a2 : 0.f, red) * (1.0f / 96.0f);
    dv = a2 - mu;
    var = blk_sum(t < 96 ? dv * dv : 0.f, red) * (1.0f / 96.0f);
    rstd = rsqrtf(var + 1e-5f);
    float r2 = 0.f;
    if (t < 96) r2 = fmaxf(dv * rstd * fc2g[t] + fc2lb[t], 0.f);

    // fc3: 96 -> 1
    float p3 = (t < 96) ? r2 * fc3W[t] : 0.f;
    float tot = blk_sum(p3, red);
    if (t == 0) out[g] = tot + fc3b[0];
}

// ---------------- launch ------------------------------------------------------
extern "C" void kernel_launch(void* const* d_in, const int* in_sizes, int n_in,
                              void* d_out, int out_size) {
    const float* x    = (const float*)d_in[0];
    const int*   ei   = (const int*)d_in[1];
    const float* ew   = (const float*)d_in[2];
    const int*   batch= (const int*)d_in[3];
    const float* ie   = (const float*)d_in[4];
    const float* Wp   = (const float*)d_in[5];
    const float* bp   = (const float*)d_in[6];
    const float* Wq   = (const float*)d_in[7];
    const float* bq   = (const float*)d_in[8];
    const float* Wk   = (const float*)d_in[9];
    const float* bk   = (const float*)d_in[10];
    const float* Wv   = (const float*)d_in[11];
    const float* bv   = (const float*)d_in[12];
    const float* We   = (const float*)d_in[13];
    const float* Ws   = (const float*)d_in[14];
    const float* bs   = (const float*)d_in[15];
    const float* lng  = (const float*)d_in[16];
    const float* lnb  = (const float*)d_in[17];
    const float* fciW = (const float*)d_in[18];
    const float* fcib = (const float*)d_in[19];
    const float* fcig = (const float*)d_in[20];
    const float* fcilb= (const float*)d_in[21];
    const float* fc1W = (const float*)d_in[22];
    const float* fc1b = (const float*)d_in[23];
    const float* fc1g = (const float*)d_in[24];
    const float* fc1lb= (const float*)d_in[25];
    const float* fc2W = (const float*)d_in[26];
    const float* fc2b = (const float*)d_in[27];
    const float* fc2g = (const float*)d_in[28];
    const float* fc2lb= (const float*)d_in[29];
    const float* fc3W = (const float*)d_in[30];
    const float* fc3b = (const float*)d_in[31];
    float* out = (float*)d_out;

    const int* src = ei;
    const int* dst = ei + EE;

    proj_kernel<<<(NN * HD + 255) / 256, 256>>>(x, Wp, bp);
    split_w_kernel<<<(12 * KSTEPS * 24 * 32 + 255) / 256, 256>>>(Wq, Wk, Wv, Ws);

    for (int i = 0; i < 3; i++) {
        split_h_kernel<<<NTILES * KSTEPS * 2 * 32 / 256, 256>>>();
        gemm_tc_kernel<<<dim3(NTILES / 4, 4), 256>>>(i, bq, bk, bv, bs);
        init_layer_kernel<<<(NN * HD + 255) / 256, 256>>>();
        edge_logits_kernel<<<EE / 8, 256>>>(src, dst, ew, We + i * HD);
        edge_agg_kernel<<<EE / 8, 256>>>(src, dst, ew, We + i * HD);
        ln_res_kernel<<<NN / 8, 256>>>(lng + i * HD, lnb + i * HD);
    }

    pool_init_kernel<<<(GG * HD + 255) / 256, 256>>>();
    pool_kernel<<<512, HD>>>(batch);
    head_kernel<<<GG, HD>>>(ie, fciW, fcib, fcig, fcilb,
                            fc1W, fc1b, fc1g, fc1lb,
                            fc2W, fc2b, fc2g, fc2lb,
                            fc3W, fc3b, out);
}

// round 8
// speedup vs baseline: 3.4542x; 1.2600x over previous
#include <cuda_runtime.h>
#include <cuda_fp16.h>
#include <math.h>
#include <float.h>
#include <stdint.h>

#define NN 100000
#define EE 400000
#define GG 32
#define HH 6
#define HD 192
#define NTILES 6256          // ceil(100000/16)=6250, padded to multiple of 8
#define KSTEPS 12            // 192/16
#define SCAN_BLOCKS 196      // ceil(100000/512)

// ---------------- scratch (device globals; no allocations allowed) ----------
__device__ float g_h[NN * HD];
__device__ __half g_qh[NN * HD];
__device__ __half g_kh[NN * HD];
__device__ __half g_vh[NN * HD];
__device__ float g_s[NN * HD];
__device__ float g_pool[GG * HD];
__device__ float g_cnt[GG];

// CSR (built once; edge_index constant across layers)
__device__ int g_deg[NN];
__device__ int g_off[NN];
__device__ int g_cur[NN];
__device__ int g_bsum[256];
__device__ int2 g_edge[EE];          // (src, edge_weight bits)

// fp16x2 fragment operands for mma.sync, pre-paired as u64 for LDG.64
__device__ unsigned long long g_afrag[(size_t)NTILES * KSTEPS * 2 * 32];   // 38.4MB
__device__ unsigned long long g_wfrag[(size_t)12 * KSTEPS * 24 * 32];      // 0.9MB

// ---------------- helpers ---------------------------------------------------
__device__ __forceinline__ unsigned fp2(float a, float b) {
    unsigned r;
    asm("cvt.rn.f16x2.f32 %0, %1, %2;" : "=r"(r) : "f"(b), "f"(a));
    return r;
}

__device__ __forceinline__ void mma_fp16(float* c, const unsigned* a, const unsigned* b) {
    asm("mma.sync.aligned.m16n8k16.row.col.f32.f16.f16.f32 "
        "{%0,%1,%2,%3}, {%4,%5,%6,%7}, {%8,%9}, {%0,%1,%2,%3};"
        : "+f"(c[0]), "+f"(c[1]), "+f"(c[2]), "+f"(c[3])
        : "r"(a[0]), "r"(a[1]), "r"(a[2]), "r"(a[3]), "r"(b[0]), "r"(b[1]));
}

// block reduce over 192 threads (6 warps)
__device__ __forceinline__ float blk_sum(float v, float* red) {
    int t = threadIdx.x, lane = t & 31, w = t >> 5;
#pragma unroll
    for (int o = 16; o; o >>= 1) v += __shfl_xor_sync(0xffffffffu, v, o);
    __syncthreads();
    if (lane == 0) red[w] = v;
    __syncthreads();
    float s = 0.f;
#pragma unroll
    for (int i = 0; i < 6; i++) s += red[i];
    return s;
}

// ---------------- input projection: h = x @ Wp + bp -------------------------
__global__ void proj_kernel(const float* __restrict__ x,
                            const float* __restrict__ Wp,
                            const float* __restrict__ bp) {
    int i = blockIdx.x * blockDim.x + threadIdx.x;
    if (i >= NN * HD) return;
    int n = i / HD, d = i - n * HD;
    const float* xr = x + n * 4;
    float acc = bp[d];
    acc += xr[0] * Wp[d] + xr[1] * Wp[HD + d] + xr[2] * Wp[2 * HD + d] + xr[3] * Wp[3 * HD + d];
    g_h[i] = acc;
}

// ---------------- CSR build (once per launch) -------------------------------
__global__ void deg_zero_kernel() {
    int i = blockIdx.x * 256 + threadIdx.x;
    if (i < NN) g_deg[i] = 0;
}
__global__ void hist_kernel(const int* __restrict__ dst) {
    int e = blockIdx.x * 256 + threadIdx.x;
    if (e < EE) atomicAdd(&g_deg[dst[e]], 1);
}
__global__ void scan1_kernel() {   // 196 blocks x 512: per-block exclusive scan
    __shared__ int sh[512];
    int i = blockIdx.x * 512 + threadIdx.x;
    int v = (i < NN) ? g_deg[i] : 0;
    sh[threadIdx.x] = v;
    __syncthreads();
#pragma unroll
    for (int o = 1; o < 512; o <<= 1) {
        int t = (threadIdx.x >= o) ? sh[threadIdx.x - o] : 0;
        __syncthreads();
        sh[threadIdx.x] += t;
        __syncthreads();
    }
    if (i < NN) g_off[i] = sh[threadIdx.x] - v;
    if (threadIdx.x == 511) g_bsum[blockIdx.x] = sh[511];
}
__global__ void scan2_kernel() {   // 1 block x 256: scan the block sums
    __shared__ int sh[256];
    int v = (threadIdx.x < SCAN_BLOCKS) ? g_bsum[threadIdx.x] : 0;
    sh[threadIdx.x] = v;
    __syncthreads();
#pragma unroll
    for (int o = 1; o < 256; o <<= 1) {
        int t = (threadIdx.x >= o) ? sh[threadIdx.x - o] : 0;
        __syncthreads();
        sh[threadIdx.x] += t;
        __syncthreads();
    }
    g_bsum[threadIdx.x] = sh[threadIdx.x] - v;   // exclusive
}
__global__ void scan3_kernel() {
    int i = blockIdx.x * 256 + threadIdx.x;
    if (i >= NN) return;
    int o = g_off[i] + g_bsum[i >> 9];
    g_off[i] = o;
    g_cur[i] = o;
}
__global__ void scatter_kernel(const int* __restrict__ src, const int* __restrict__ dst,
                               const float* __restrict__ ew) {
    int e = blockIdx.x * 256 + threadIdx.x;
    if (e >= EE) return;
    int d = dst[e];
    int pos = atomicAdd(&g_cur[d], 1);
    g_edge[pos] = make_int2(src[e], __float_as_int(ew[e]));
}

// ---------------- convert h into A-fragment layout (fp16 pairs) -------------
__global__ void split_h_kernel() {
    int t = blockIdx.x * 256 + threadIdx.x;
    int lane = t & 31;
    int p = (t >> 5) & 1;
    int ks = (t >> 6) % KSTEPS;
    int tile = t / (KSTEPS * 2 * 32);
    int row = tile * 16 + (lane >> 2);
    int k = ks * 16 + ((lane & 3) << 1) + (p << 3);
    float x0 = 0.f, x1 = 0.f, x2 = 0.f, x3 = 0.f;
    if (row < NN) {
        const float* q = &g_h[row * HD + k];
        x0 = q[0]; x1 = q[1];
    }
    if (row + 8 < NN) {
        const float* q = &g_h[(row + 8) * HD + k];
        x2 = q[0]; x3 = q[1];
    }
    unsigned lo = fp2(x0, x1);
    unsigned hi = fp2(x2, x3);
    g_afrag[t] = ((unsigned long long)hi << 32) | lo;
}

// ---------------- convert all 12 weight matrices into B-fragment layout -----
__global__ void split_w_kernel(const float* __restrict__ Wq, const float* __restrict__ Wk,
                               const float* __restrict__ Wv, const float* __restrict__ Ws) {
    int t = blockIdx.x * 256 + threadIdx.x;
    if (t >= 12 * KSTEPS * 24 * 32) return;
    int lane = t & 31;
    int nt = (t >> 5) % 24;
    int ks = ((t >> 5) / 24) % KSTEPS;
    int mat = t / (32 * 24 * KSTEPS);
    int n = nt * 8 + (lane >> 2);
    int k = ks * 16 + ((lane & 3) << 1);
    int which = mat & 3, layer = mat >> 2;
    const float* W = (which == 0 ? Wq : which == 1 ? Wk : which == 2 ? Wv : Ws)
                     + (size_t)layer * HD * HD;
    unsigned lo = fp2(W[k * HD + n], W[(k + 1) * HD + n]);
    unsigned hi = fp2(W[(k + 8) * HD + n], W[(k + 9) * HD + n]);
    g_wfrag[t] = ((unsigned long long)hi << 32) | lo;
}

// ---------------- tensor-core GEMM: O = h @ W + b (single-pass fp16) --------
__global__ __launch_bounds__(256, 3) void gemm_tc_kernel(
    int layer,
    const float* __restrict__ bq, const float* __restrict__ bk,
    const float* __restrict__ bv, const float* __restrict__ bs) {
    int w = threadIdx.x >> 5, lane = threadIdx.x & 31;
    int wm = w & 1, wn = w >> 1;
    int tile0 = blockIdx.x * 4 + wm * 2;
    int mat = layer * 4 + blockIdx.y;

    float C[2][6][4];
#pragma unroll
    for (int mt = 0; mt < 2; mt++)
#pragma unroll
        for (int nt = 0; nt < 6; nt++)
#pragma unroll
            for (int i = 0; i < 4; i++) C[mt][nt][i] = 0.f;

    const unsigned long long* __restrict__ A = g_afrag;
    const unsigned long long* __restrict__ B =
        g_wfrag + (size_t)mat * KSTEPS * 24 * 32;

#pragma unroll 3
    for (int ks = 0; ks < KSTEPS; ks++) {
        unsigned a[2][4];
#pragma unroll
        for (int mt = 0; mt < 2; mt++) {
            size_t base = (((size_t)(tile0 + mt) * KSTEPS + ks) * 2) * 32 + lane;
            unsigned long long v0 = __ldg(&A[base]);
            unsigned long long v1 = __ldg(&A[base + 32]);
            a[mt][0] = (unsigned)v0; a[mt][1] = (unsigned)(v0 >> 32);
            a[mt][2] = (unsigned)v1; a[mt][3] = (unsigned)(v1 >> 32);
        }
#pragma unroll
        for (int nt = 0; nt < 6; nt++) {
            int ntg = wn * 6 + nt;
            unsigned long long bv = __ldg(&B[((size_t)ks * 24 + ntg) * 32 + lane]);
            unsigned b[2] = {(unsigned)bv, (unsigned)(bv >> 32)};
#pragma unroll
            for (int mt = 0; mt < 2; mt++) mma_fp16(C[mt][nt], a[mt], b);
        }
    }

    const float* Bv = ((blockIdx.y == 0) ? bq : (blockIdx.y == 1) ? bk
                     : (blockIdx.y == 2) ? bv : bs) + layer * HD;
    if (blockIdx.y < 3) {
        __half* O = (blockIdx.y == 0) ? g_qh : (blockIdx.y == 1) ? g_kh : g_vh;
#pragma unroll
        for (int mt = 0; mt < 2; mt++) {
            int r0 = (tile0 + mt) * 16 + (lane >> 2);
#pragma unroll
            for (int nt = 0; nt < 6; nt++) {
                int c = (wn * 6 + nt) * 8 + (lane & 3) * 2;
                float b0 = Bv[c], b1 = Bv[c + 1];
                if (r0 < NN)
                    *reinterpret_cast<__half2*>(&O[r0 * HD + c]) =
                        __floats2half2_rn(C[mt][nt][0] + b0, C[mt][nt][1] + b1);
                int r1 = r0 + 8;
                if (r1 < NN)
                    *reinterpret_cast<__half2*>(&O[r1 * HD + c]) =
                        __floats2half2_rn(C[mt][nt][2] + b0, C[mt][nt][3] + b1);
            }
        }
    } else {
#pragma unroll
        for (int mt = 0; mt < 2; mt++) {
            int r0 = (tile0 + mt) * 16 + (lane >> 2);
#pragma unroll
            for (int nt = 0; nt < 6; nt++) {
                int c = (wn * 6 + nt) * 8 + (lane & 3) * 2;
                float b0 = Bv[c], b1 = Bv[c + 1];
                if (r0 < NN) {
                    float2 o = {C[mt][nt][0] + b0, C[mt][nt][1] + b1};
                    *reinterpret_cast<float2*>(&g_s[r0 * HD + c]) = o;
                }
                int r1 = r0 + 8;
                if (r1 < NN) {
                    float2 o = {C[mt][nt][2] + b0, C[mt][nt][3] + b1};
                    *reinterpret_cast<float2*>(&g_s[r1 * HD + c]) = o;
                }
            }
        }
    }
}

// ---------------- fused node attention: warp per dst node -------------------
// lane owns half2 idx 32j+lane (dims 64j+2lane(+1)); head = 2j + (lane>=16).
// online softmax over CSR edges; epilogue: /z, +skip, LN, relu, h +=.
__global__ __launch_bounds__(256) void node_attn_kernel(
    const float* __restrict__ lnw, const float* __restrict__ lnb,
    const float* __restrict__ We) {
    int n = blockIdx.x * 8 + (threadIdx.x >> 5);
    int lane = threadIdx.x & 31;
    if (n >= NN) return;
    int off = g_off[n], deg = g_deg[n];

    const __half2* Q2 = (const __half2*)g_qh + (size_t)n * 96;
    const float2* We2 = (const float2*)We;
    float2 q[3], we[3];
#pragma unroll
    for (int j = 0; j < 3; j++) {
        q[j] = __half22float2(Q2[32 * j + lane]);
        we[j] = We2[32 * j + lane];
    }
    float m[3] = {-FLT_MAX, -FLT_MAX, -FLT_MAX};
    float z[3] = {0.f, 0.f, 0.f};
    float2 va[3] = {{0.f, 0.f}, {0.f, 0.f}, {0.f, 0.f}};
    const float scale = 0.17677669529663687f;  // 1/sqrt(32)

    int2 em = make_int2(0, 0);
    __half2 kb[3], vb[3];
    if (deg > 0) {
        em = __ldg(&g_edge[off]);
        const __half2* K2 = (const __half2*)g_kh + (size_t)em.x * 96;
        const __half2* V2 = (const __half2*)g_vh + (size_t)em.x * 96;
#pragma unroll
        for (int j = 0; j < 3; j++) { kb[j] = K2[32 * j + lane]; vb[j] = V2[32 * j + lane]; }
    }

    for (int i = 0; i < deg; i++) {
        float w = __int_as_float(em.y);
        float2 kf[3], vf[3];
#pragma unroll
        for (int j = 0; j < 3; j++) { kf[j] = __half22float2(kb[j]); vf[j] = __half22float2(vb[j]); }

        // prefetch next edge
        int2 emn = em;
        if (i + 1 < deg) {
            emn = __ldg(&g_edge[off + i + 1]);
            const __half2* K2 = (const __half2*)g_kh + (size_t)emn.x * 96;
            const __half2* V2 = (const __half2*)g_vh + (size_t)emn.x * 96;
#pragma unroll
            for (int j = 0; j < 3; j++) { kb[j] = K2[32 * j + lane]; vb[j] = V2[32 * j + lane]; }
        }

        float acc[3];
#pragma unroll
        for (int j = 0; j < 3; j++) {
            float kex = kf[j].x + w * we[j].x;
            float key = kf[j].y + w * we[j].y;
            acc[j] = q[j].x * kex + q[j].y * key;
        }
#pragma unroll
        for (int o = 8; o; o >>= 1) {
#pragma unroll
            for (int j = 0; j < 3; j++) acc[j] += __shfl_xor_sync(0xffffffffu, acc[j], o);
        }
#pragma unroll
        for (int j = 0; j < 3; j++) {
            float lgt = acc[j] * scale;
            float mn = fmaxf(m[j], lgt);
            float corr = __expf(m[j] - mn);
            float p = __expf(lgt - mn);
            z[j] = z[j] * corr + p;
            float vex = vf[j].x + w * we[j].x;
            float vey = vf[j].y + w * we[j].y;
            va[j].x = va[j].x * corr + p * vex;
            va[j].y = va[j].y * corr + p * vey;
            m[j] = mn;
        }
        em = emn;
    }

    // epilogue: val = va/z + skip; LN over 192 dims; relu; h +=
    const float2* S2 = (const float2*)g_s + (size_t)n * 96;
    float2 val[3];
    float s1 = 0.f;
#pragma unroll
    for (int j = 0; j < 3; j++) {
        float inv = (z[j] > 0.f) ? (1.0f / z[j]) : 0.f;
        float2 sv = S2[32 * j + lane];
        val[j].x = va[j].x * inv + sv.x;
        val[j].y = va[j].y * inv + sv.y;
        s1 += val[j].x + val[j].y;
    }
#pragma unroll
    for (int o = 16; o; o >>= 1) s1 += __shfl_xor_sync(0xffffffffu, s1, o);
    float mu = s1 * (1.0f / HD);
    float s2 = 0.f;
#pragma unroll
    for (int j = 0; j < 3; j++) {
        float dx = val[j].x - mu, dy = val[j].y - mu;
        s2 += dx * dx + dy * dy;
    }
#pragma unroll
    for (int o = 16; o; o >>= 1) s2 += __shfl_xor_sync(0xffffffffu, s2, o);
    float rstd = rsqrtf(s2 * (1.0f / HD) + 1e-5f);

    const float2* LG2 = (const float2*)lnw;
    const float2* LB2 = (const float2*)lnb;
    float2* H2 = (float2*)g_h + (size_t)n * 96;
#pragma unroll
    for (int j = 0; j < 3; j++) {
        int idx = 32 * j + lane;
        float2 gv = LG2[idx], bv = LB2[idx], hv = H2[idx];
        float yx = (val[j].x - mu) * rstd * gv.x + bv.x;
        float yy = (val[j].y - mu) * rstd * gv.y + bv.y;
        hv.x += fmaxf(yx, 0.f);
        hv.y += fmaxf(yy, 0.f);
        H2[idx] = hv;
    }
}

// ---------------- pooling ----------------------------------------------------
__global__ void pool_init_kernel() {
    int i = blockIdx.x * blockDim.x + threadIdx.x;
    if (i < GG * HD) g_pool[i] = 0.f;
    if (i < GG) g_cnt[i] = 0.f;
}

__global__ void pool_kernel(const int* __restrict__ batch) {
    __shared__ float acc[GG * HD];
    __shared__ float scnt[GG];
    int t = threadIdx.x;  // 192
    for (int i = t; i < GG * HD; i += HD) acc[i] = 0.f;
    if (t < GG) scnt[t] = 0.f;
    __syncthreads();
    int per = (NN + gridDim.x - 1) / gridDim.x;
    int n0 = blockIdx.x * per;
    int n1 = min(n0 + per, NN);
    for (int n = n0; n < n1; n++) {
        int g = batch[n];
        acc[g * HD + t] += g_h[n * HD + t];
        if (t == 0) scnt[g] += 1.f;
    }
    __syncthreads();
    for (int i = t; i < GG * HD; i += HD) atomicAdd(&g_pool[i], acc[i]);
    if (t < GG) atomicAdd(&g_cnt[t], scnt[t]);
}

// ---------------- head MLP (block per graph, 192 threads) -------------------
__global__ void head_kernel(const float* __restrict__ ie,
                            const float* __restrict__ fciW, const float* __restrict__ fcib,
                            const float* __restrict__ fcig, const float* __restrict__ fcilb,
                            const float* __restrict__ fc1W, const float* __restrict__ fc1b,
                            const float* __restrict__ fc1g, const float* __restrict__ fc1lb,
                            const float* __restrict__ fc2W, const float* __restrict__ fc2b,
                            const float* __restrict__ fc2g, const float* __restrict__ fc2lb,
                            const float* __restrict__ fc3W, const float* __restrict__ fc3b,
                            float* __restrict__ out) {
    __shared__ float zin[2 * HD];
    __shared__ float buf[HD];
    __shared__ float red[8];
    int t = threadIdx.x;  // 0..191
    int g = blockIdx.x;

    float cnt = fmaxf(g_cnt[g], 1.f);
    zin[t] = g_pool[g * HD + t] / cnt;

    // fc_initial: Linear(1,192) + LN + ReLU
    float iv = ie[g] * fciW[t] + fcib[t];
    float mu = blk_sum(iv, red) * (1.0f / HD);
    float dv = iv - mu;
    float var = blk_sum(dv * dv, red) * (1.0f / HD);
    float rstd = rsqrtf(var + 1e-5f);
    zin[HD + t] = fmaxf(dv * rstd * fcig[t] + fcilb[t], 0.f);
    __syncthreads();

    // fc1: 384 -> 192, LN, ReLU
    float a = fc1b[t];
    for (int k = 0; k < 2 * HD; k++) a += zin[k] * fc1W[k * HD + t];
    mu = blk_sum(a, red) * (1.0f / HD);
    dv = a - mu;
    var = blk_sum(dv * dv, red) * (1.0f / HD);
    rstd = rsqrtf(var + 1e-5f);
    buf[t] = fmaxf(dv * rstd * fc1g[t] + fc1lb[t], 0.f);
    __syncthreads();

    // fc2: 192 -> 96, LN, ReLU
    float a2 = 0.f;
    if (t < 96) {
        a2 = fc2b[t];
        for (int k = 0; k < HD; k++) a2 += buf[k] * fc2W[k * 96 + t];
    }
    mu = blk_sum(t < 96 ? a2 : 0.f, red) * (1.0f / 96.0f);
    dv = a2 - mu;
    var = blk_sum(t < 96 ? dv * dv : 0.f, red) * (1.0f / 96.0f);
    rstd = rsqrtf(var + 1e-5f);
    float r2 = 0.f;
    if (t < 96) r2 = fmaxf(dv * rstd * fc2g[t] + fc2lb[t], 0.f);

    // fc3: 96 -> 1
    float p3 = (t < 96) ? r2 * fc3W[t] : 0.f;
    float tot = blk_sum(p3, red);
    if (t == 0) out[g] = tot + fc3b[0];
}

// ---------------- launch ------------------------------------------------------
extern "C" void kernel_launch(void* const* d_in, const int* in_sizes, int n_in,
                              void* d_out, int out_size) {
    const float* x    = (const float*)d_in[0];
    const int*   ei   = (const int*)d_in[1];
    const float* ew   = (const float*)d_in[2];
    const int*   batch= (const int*)d_in[3];
    const float* ie   = (const float*)d_in[4];
    const float* Wp   = (const float*)d_in[5];
    const float* bp   = (const float*)d_in[6];
    const float* Wq   = (const float*)d_in[7];
    const float* bq   = (const float*)d_in[8];
    const float* Wk   = (const float*)d_in[9];
    const float* bk   = (const float*)d_in[10];
    const float* Wv   = (const float*)d_in[11];
    const float* bv   = (const float*)d_in[12];
    const float* We   = (const float*)d_in[13];
    const float* Ws   = (const float*)d_in[14];
    const float* bs   = (const float*)d_in[15];
    const float* lng  = (const float*)d_in[16];
    const float* lnb  = (const float*)d_in[17];
    const float* fciW = (const float*)d_in[18];
    const float* fcib = (const float*)d_in[19];
    const float* fcig = (const float*)d_in[20];
    const float* fcilb= (const float*)d_in[21];
    const float* fc1W = (const float*)d_in[22];
    const float* fc1b = (const float*)d_in[23];
    const float* fc1g = (const float*)d_in[24];
    const float* fc1lb= (const float*)d_in[25];
    const float* fc2W = (const float*)d_in[26];
    const float* fc2b = (const float*)d_in[27];
    const float* fc2g = (const float*)d_in[28];
    const float* fc2lb= (const float*)d_in[29];
    const float* fc3W = (const float*)d_in[30];
    const float* fc3b = (const float*)d_in[31];
    float* out = (float*)d_out;

    const int* src = ei;
    const int* dst = ei + EE;

    proj_kernel<<<(NN * HD + 255) / 256, 256>>>(x, Wp, bp);
    split_w_kernel<<<(12 * KSTEPS * 24 * 32 + 255) / 256, 256>>>(Wq, Wk, Wv, Ws);

    // CSR build (edge_index constant across layers)
    deg_zero_kernel<<<(NN + 255) / 256, 256>>>();
    hist_kernel<<<(EE + 255) / 256, 256>>>(dst);
    scan1_kernel<<<SCAN_BLOCKS, 512>>>();
    scan2_kernel<<<1, 256>>>();
    scan3_kernel<<<(NN + 255) / 256, 256>>>();
    scatter_kernel<<<(EE + 255) / 256, 256>>>(src, dst, ew);

    for (int i = 0; i < 3; i++) {
        split_h_kernel<<<NTILES * KSTEPS * 2 * 32 / 256, 256>>>();
        gemm_tc_kernel<<<dim3(NTILES / 4, 4), 256>>>(i, bq, bk, bv, bs);
        node_attn_kernel<<<(NN + 7) / 8, 256>>>(lng + i * HD, lnb + i * HD, We + i * HD);
    }

    pool_init_kernel<<<(GG * HD + 255) / 256, 256>>>();
    pool_kernel<<<512, HD>>>(batch);
    head_kernel<<<GG, HD>>>(ie, fciW, fcib, fcig, fcilb,
                            fc1W, fc1b, fc1g, fc1lb,
                            fc2W, fc2b, fc2g, fc2lb,
                            fc3W, fc3b, out);
}